// round 3
// baseline (speedup 1.0000x reference)
#include <cuda_runtime.h>
#include <math.h>
#include <stddef.h>

#define N_ 50000
#define E_ 600000

// ---------------- device scratch (static: no allocations allowed) ----------
__device__ int      g_src[E_];
__device__ int      g_dst[E_];
__device__ int      g_deg[N_];
__device__ float    g_dinv[N_];
__device__ int      g_flag;            // 1 = edge_index is int64, 0 = int32
__device__ float    g_als[N_ * 2];
__device__ float    g_ald[N_ * 2];
__device__ unsigned g_menc[N_ * 2];    // order-encoded float max
__device__ float    g_m[N_ * 2];       // decoded max
__device__ float    g_den[N_ * 2];     // softmax denominator
__device__ float    g_bufA[N_ * 256];  // GEMM outputs (max width 256)
__device__ float    g_bufB[N_ * 256];  // aggregation numerators
__device__ float    g_bufC[N_ * 128];  // activations between stages

// ---------------- helpers --------------------------------------------------
__device__ __forceinline__ float lrelu(float e) { return e > 0.f ? e : 0.2f * e; }

// order-preserving float<->uint encoding for atomicMax on floats
__device__ __forceinline__ unsigned enc(float f) {
    unsigned u = __float_as_uint(f);
    return (u & 0x80000000u) ? ~u : (u | 0x80000000u);
}
__device__ __forceinline__ float dec(unsigned u) {
    return (u & 0x80000000u) ? __uint_as_float(u & 0x7fffffffu)
                             : __uint_as_float(~u);
}

__device__ __forceinline__ float wred_sum(float v) {
#pragma unroll
    for (int o = 16; o; o >>= 1) v += __shfl_xor_sync(0xffffffffu, v, o);
    return v;
}
__device__ __forceinline__ float wred_max(float v) {
#pragma unroll
    for (int o = 16; o; o >>= 1) v = fmaxf(v, __shfl_xor_sync(0xffffffffu, v, o));
    return v;
}

// vector global float reduction (sm_90+): 4 adds in one L2 op, no return
__device__ __forceinline__ void red4(float* p, float4 v) {
    unsigned long long gp = (unsigned long long)__cvta_generic_to_global(p);
    asm volatile("red.global.add.v4.f32 [%0], {%1,%2,%3,%4};"
                 :: "l"(gp), "f"(v.x), "f"(v.y), "f"(v.z), "f"(v.w)
                 : "memory");
}

// ---------------- preprocessing --------------------------------------------
__global__ void k_prep(const void* eidx) {
    int i = blockIdx.x * 256 + threadIdx.x;
    if (i < N_) g_deg[i] = 0;
    if (i == 0) {
        // detect int64 vs int32: int64 data -> all of the first 128 int64
        // reads are valid node ids; int32 data read as int64 is huge w.h.p.
        const long long* p = (const long long*)eidx;
        int ok = 1;
        for (int j = 0; j < 128; j++) {
            long long v = p[j];
            if (v < 0 || v >= N_) { ok = 0; break; }
        }
        g_flag = ok;
    }
}

__global__ void k_convert(const void* eidx) {
    int i = blockIdx.x * 256 + threadIdx.x;
    if (i >= E_) return;
    int s, d;
    if (g_flag) {
        const long long* p = (const long long*)eidx;
        s = (int)p[i]; d = (int)p[E_ + i];
    } else {
        const int* p = (const int*)eidx;
        s = p[i]; d = p[E_ + i];
    }
    g_src[i] = s; g_dst[i] = d;
    atomicAdd(&g_deg[d], 1);
}

__global__ void k_dinv() {
    int i = blockIdx.x * 256 + threadIdx.x;
    if (i < N_) g_dinv[i] = rsqrtf((float)(g_deg[i] + 1));  // +1 self loop
}

// ---------------- fp32 GEMM: C[N,CO] = A[N,128] @ W[128,CO] ----------------
__global__ void __launch_bounds__(256) k_gemm(const float* __restrict__ A,
                                              const float* __restrict__ W,
                                              float* __restrict__ C, int CO) {
    __shared__ float As[64][68];  // [k][m], padded
    __shared__ float Ws[64][64];  // [k][n]
    int bm = blockIdx.x * 64, bn = blockIdx.y * 64;
    int tid = threadIdx.x, tx = tid & 15, ty = tid >> 4;
    int row = tid >> 2, q = tid & 3;

    float acc[4][4];
#pragma unroll
    for (int i = 0; i < 4; i++)
#pragma unroll
        for (int j = 0; j < 4; j++) acc[i][j] = 0.f;

    for (int k0 = 0; k0 < 128; k0 += 64) {
        int gr = bm + row;
#pragma unroll
        for (int v = 0; v < 4; v++) {
            int kk = q * 16 + v * 4;
            float4 f = make_float4(0.f, 0.f, 0.f, 0.f);
            if (gr < N_) f = *(const float4*)(A + (size_t)gr * 128 + k0 + kk);
            As[kk + 0][row] = f.x; As[kk + 1][row] = f.y;
            As[kk + 2][row] = f.z; As[kk + 3][row] = f.w;
        }
#pragma unroll
        for (int v = 0; v < 4; v++) {
            int c4 = q + v * 4;
            *(float4*)&Ws[row][c4 * 4] =
                *(const float4*)(W + (size_t)(k0 + row) * CO + bn + c4 * 4);
        }
        __syncthreads();
#pragma unroll
        for (int kk = 0; kk < 64; kk++) {
            float4 a = *(const float4*)&As[kk][ty * 4];
            float4 w = *(const float4*)&Ws[kk][tx * 4];
            acc[0][0] += a.x * w.x; acc[0][1] += a.x * w.y; acc[0][2] += a.x * w.z; acc[0][3] += a.x * w.w;
            acc[1][0] += a.y * w.x; acc[1][1] += a.y * w.y; acc[1][2] += a.y * w.z; acc[1][3] += a.y * w.w;
            acc[2][0] += a.z * w.x; acc[2][1] += a.z * w.y; acc[2][2] += a.z * w.z; acc[2][3] += a.z * w.w;
            acc[3][0] += a.w * w.x; acc[3][1] += a.w * w.y; acc[3][2] += a.w * w.z; acc[3][3] += a.w * w.w;
        }
        __syncthreads();
    }
#pragma unroll
    for (int i = 0; i < 4; i++) {
        int r = bm + ty * 4 + i;
        if (r < N_) {
            float4 o = make_float4(acc[i][0], acc[i][1], acc[i][2], acc[i][3]);
            *(float4*)(C + (size_t)r * CO + bn + tx * 4) = o;
        }
    }
}

// ---------------- GCN ------------------------------------------------------
__global__ void k_gcn_self(float* __restrict__ out, const float* __restrict__ h) {
    int idx = blockIdx.x * 256 + threadIdx.x;
    if (idx >= N_ * 128) return;
    int n = idx >> 7;
    float di = g_dinv[n];
    out[idx] = di * di * h[idx];
}

__global__ void __launch_bounds__(256) k_gcn_scatter(const float* __restrict__ h,
                                                     float* __restrict__ out) {
    int gw = (blockIdx.x * 256 + threadIdx.x) >> 5;
    if (gw >= E_) return;
    int lane = threadIdx.x & 31;
    int s = g_src[gw], d = g_dst[gw];
    float w = g_dinv[s] * g_dinv[d];
    float4 v = *(const float4*)(h + (size_t)s * 128 + lane * 4);
    red4(out + (size_t)d * 128 + lane * 4,
         make_float4(v.x * w, v.y * w, v.z * w, v.w * w));
}

__global__ void k_bnrelu(float* __restrict__ out, const float* __restrict__ in,
                         const float* __restrict__ b, const float* __restrict__ gamma,
                         const float* __restrict__ beta, const float* __restrict__ mean,
                         const float* __restrict__ var) {
    int idx = blockIdx.x * 256 + threadIdx.x;
    if (idx >= N_ * 128) return;
    int c = idx & 127;
    float v = in[idx] + b[c];
    v = (v - mean[c]) * rsqrtf(var[c] + 1e-5f) * gamma[c] + beta[c];
    out[idx] = fmaxf(v, 0.f);
}

// ---------------- GAT ------------------------------------------------------
template <int C>
__global__ void k_al(const float* __restrict__ hg, const float* __restrict__ asrc,
                     const float* __restrict__ adst) {
    int gw = (blockIdx.x * 256 + threadIdx.x) >> 5;
    int lane = threadIdx.x & 31;
    int n = gw >> 1, h = gw & 1;
    if (n >= N_) return;
    const float* hp = hg + (size_t)n * (2 * C) + h * C;
    float s = 0.f, d = 0.f;
#pragma unroll
    for (int c = lane; c < C; c += 32) {
        float hv = hp[c];
        s += hv * asrc[h * C + c];
        d += hv * adst[h * C + c];
    }
    s = wred_sum(s); d = wred_sum(d);
    if (lane == 0) { g_als[n * 2 + h] = s; g_ald[n * 2 + h] = d; }
}

__global__ void k_gat_init() {  // seed max with the (always present) self loop
    int n = blockIdx.x * 256 + threadIdx.x;
    if (n >= N_) return;
#pragma unroll
    for (int h = 0; h < 2; h++) {
        float es = lrelu(g_als[n * 2 + h] + g_ald[n * 2 + h]);
        g_menc[n * 2 + h] = enc(es);
    }
}

__global__ void k_gat_max() {
    int i = blockIdx.x * 256 + threadIdx.x;
    if (i >= E_) return;
    int s = g_src[i], d = g_dst[i];
#pragma unroll
    for (int h = 0; h < 2; h++) {
        float e = lrelu(g_als[s * 2 + h] + g_ald[d * 2 + h]);
        atomicMax(&g_menc[d * 2 + h], enc(e));
    }
}

__global__ void k_gat_init2() {  // decode max, seed denominator with self term
    int n = blockIdx.x * 256 + threadIdx.x;
    if (n >= N_) return;
#pragma unroll
    for (int h = 0; h < 2; h++) {
        float m = dec(g_menc[n * 2 + h]);
        g_m[n * 2 + h] = m;
        float es = lrelu(g_als[n * 2 + h] + g_ald[n * 2 + h]);
        g_den[n * 2 + h] = expf(es - m);
    }
}

template <int C>
__global__ void k_self_num(float* __restrict__ num, const float* __restrict__ hg) {
    int idx = blockIdx.x * 256 + threadIdx.x;
    if (idx >= N_ * 2 * C) return;
    int n = idx / (2 * C);
    int j = idx - n * 2 * C;
    int h = j / C;
    num[idx] = g_den[n * 2 + h] * hg[idx];  // g_den == w_self here (pre-scatter)
}

template <int C>
__global__ void __launch_bounds__(256) k_gat_scatter(const float* __restrict__ hg,
                                                     float* __restrict__ num) {
    int gw = (blockIdx.x * 256 + threadIdx.x) >> 5;
    if (gw >= E_) return;
    int lane = threadIdx.x & 31;
    int s = g_src[gw], d = g_dst[gw];
    if (C == 128) {
#pragma unroll
        for (int h = 0; h < 2; h++) {
            float e = lrelu(g_als[s * 2 + h] + g_ald[d * 2 + h]);
            float w = expf(e - g_m[d * 2 + h]);
            float4 v = *(const float4*)(hg + (size_t)s * 256 + h * 128 + lane * 4);
            red4(num + (size_t)d * 256 + h * 128 + lane * 4,
                 make_float4(v.x * w, v.y * w, v.z * w, v.w * w));
            if (lane == 0) atomicAdd(&g_den[d * 2 + h], w);
        }
    } else {  // C == 64: half-warp per head
        int h = lane >> 4, cl = lane & 15;
        float e = lrelu(g_als[s * 2 + h] + g_ald[d * 2 + h]);
        float w = expf(e - g_m[d * 2 + h]);
        float4 v = *(const float4*)(hg + (size_t)s * 128 + h * 64 + cl * 4);
        red4(num + (size_t)d * 128 + h * 64 + cl * 4,
             make_float4(v.x * w, v.y * w, v.z * w, v.w * w));
        if (cl == 0) atomicAdd(&g_den[d * 2 + h], w);
    }
}

template <int C, bool RELU>
__global__ void k_gat_fin(float* __restrict__ out, const float* __restrict__ num,
                          const float* __restrict__ bias) {
    int idx = blockIdx.x * 256 + threadIdx.x;
    if (idx >= N_ * C) return;
    int n = idx / C, c = idx - n * C;
    float v = 0.5f * (num[(size_t)n * 2 * C + c] / g_den[n * 2] +
                      num[(size_t)n * 2 * C + C + c] / g_den[n * 2 + 1]) + bias[c];
    if (RELU) v = fmaxf(v, 0.f);
    out[idx] = v;
}

// ---------------- log_softmax over 64 cols ---------------------------------
__global__ void k_logsm(float* __restrict__ out, const float* __restrict__ in) {
    int gw = (blockIdx.x * 256 + threadIdx.x) >> 5;
    if (gw >= N_) return;
    int lane = threadIdx.x & 31;
    float v0 = in[gw * 64 + lane], v1 = in[gw * 64 + 32 + lane];
    float m = wred_max(fmaxf(v0, v1));
    float s = wred_sum(expf(v0 - m) + expf(v1 - m));
    float l = logf(s);
    out[gw * 64 + lane] = v0 - m - l;
    out[gw * 64 + 32 + lane] = v1 - m - l;
}

// ---------------- launch ----------------------------------------------------
extern "C" void kernel_launch(void* const* d_in, const int* in_sizes, int n_in,
                              void* d_out, int out_size) {
    const float* x   = (const float*)d_in[0];
    const void*  ei  = d_in[1];
    const float* Wg1 = (const float*)d_in[2];
    const float* bg1 = (const float*)d_in[3];
    const float* g1g = (const float*)d_in[4];
    const float* g1b = (const float*)d_in[5];
    const float* g1m = (const float*)d_in[6];
    const float* g1v = (const float*)d_in[7];
    const float* Wa1 = (const float*)d_in[8];
    const float* as1 = (const float*)d_in[9];
    const float* ad1 = (const float*)d_in[10];
    const float* ba1 = (const float*)d_in[11];
    const float* Wg2 = (const float*)d_in[12];
    const float* bg2 = (const float*)d_in[13];
    const float* g2g = (const float*)d_in[14];
    const float* g2b = (const float*)d_in[15];
    const float* g2m = (const float*)d_in[16];
    const float* g2v = (const float*)d_in[17];
    const float* Wa2 = (const float*)d_in[18];
    const float* as2 = (const float*)d_in[19];
    const float* ad2 = (const float*)d_in[20];
    const float* ba2 = (const float*)d_in[21];
    float* out = (float*)d_out;

    float *bufA, *bufB, *bufC;
    cudaGetSymbolAddress((void**)&bufA, g_bufA);
    cudaGetSymbolAddress((void**)&bufB, g_bufB);
    cudaGetSymbolAddress((void**)&bufC, g_bufC);

    const int TB = 256;
    const int nb = (N_ + TB - 1) / TB;   // node-parallel
    const int eb = (E_ + TB - 1) / TB;   // edge-parallel (thread per edge)
    const int ew = E_ / 8;               // edge-parallel (warp per edge)
    const int aw = (2 * N_) / 8;         // warp per (node, head)

    k_prep<<<nb, TB>>>(ei);
    k_convert<<<eb, TB>>>(ei);
    k_dinv<<<nb, TB>>>();

    // ---- GCN1 + BN1 + ReLU
    k_gemm<<<dim3(782, 2), TB>>>(x, Wg1, bufA, 128);
    k_gcn_self<<<(N_ * 128) / TB, TB>>>(bufB, bufA);
    k_gcn_scatter<<<ew, TB>>>(bufA, bufB);
    k_bnrelu<<<(N_ * 128) / TB, TB>>>(bufC, bufB, bg1, g1g, g1b, g1m, g1v);

    // ---- GAT1 + ReLU
    k_gemm<<<dim3(782, 4), TB>>>(bufC, Wa1, bufA, 256);
    k_al<128><<<aw, TB>>>(bufA, as1, ad1);
    k_gat_init<<<nb, TB>>>();
    k_gat_max<<<eb, TB>>>();
    k_gat_init2<<<nb, TB>>>();
    k_self_num<128><<<(N_ * 256) / TB, TB>>>(bufB, bufA);
    k_gat_scatter<128><<<ew, TB>>>(bufA, bufB);
    k_gat_fin<128, true><<<(N_ * 128) / TB, TB>>>(bufC, bufB, ba1);

    // ---- GCN2 + BN2 + ReLU
    k_gemm<<<dim3(782, 2), TB>>>(bufC, Wg2, bufA, 128);
    k_gcn_self<<<(N_ * 128) / TB, TB>>>(bufB, bufA);
    k_gcn_scatter<<<ew, TB>>>(bufA, bufB);
    k_bnrelu<<<(N_ * 128) / TB, TB>>>(bufC, bufB, bg2, g2g, g2b, g2m, g2v);

    // ---- GAT2 (no relu) + log_softmax
    k_gemm<<<dim3(782, 2), TB>>>(bufC, Wa2, bufA, 128);
    k_al<64><<<aw, TB>>>(bufA, as2, ad2);
    k_gat_init<<<nb, TB>>>();
    k_gat_max<<<eb, TB>>>();
    k_gat_init2<<<nb, TB>>>();
    k_self_num<64><<<(N_ * 128) / TB, TB>>>(bufB, bufA);
    k_gat_scatter<64><<<ew, TB>>>(bufA, bufB);
    k_gat_fin<64, false><<<(N_ * 64) / TB, TB>>>(bufC, bufB, ba2);
    k_logsm<<<N_ / 8, TB>>>(out, bufC);
}

// round 5
// speedup vs baseline: 1.5133x; 1.5133x over previous
#include <cuda_runtime.h>
#include <math.h>
#include <stddef.h>

#define N_ 50000
#define E_ 600000

// ---------------- device scratch (no allocations allowed) -------------------
__device__ int      g_src[E_];
__device__ int      g_dst[E_];
__device__ int      g_esrc[E_];         // CSR: src ids sorted by dst segment
__device__ int      g_rowstart[N_ + 1]; // CSR offsets
__device__ int      g_deg[N_];
__device__ int      g_fill[N_];
__device__ float    g_dinv[N_];
__device__ int      g_flag;             // 1 = edge_index is int64, 0 = int32
__device__ float    g_als[N_ * 2];
__device__ float    g_ald[N_ * 2];
__device__ float    g_bufA[N_ * 256];   // GEMM outputs (max width 256)
__device__ float    g_bufC[N_ * 128];   // activations between stages

// ---------------- helpers ---------------------------------------------------
__device__ __forceinline__ float lrelu(float e) { return e > 0.f ? e : 0.2f * e; }

__device__ __forceinline__ float wred_sum(float v) {
#pragma unroll
    for (int o = 16; o; o >>= 1) v += __shfl_xor_sync(0xffffffffu, v, o);
    return v;
}

// ---------------- preprocessing ---------------------------------------------
__global__ void k_prep(const void* eidx) {
    int i = blockIdx.x * 256 + threadIdx.x;
    if (i < N_) g_deg[i] = 0;
    if (i == 0) {
        // detect int64 vs int32: int64 -> first 128 int64 reads all valid ids
        const long long* p = (const long long*)eidx;
        int ok = 1;
        for (int j = 0; j < 128; j++) {
            long long v = p[j];
            if (v < 0 || v >= N_) { ok = 0; break; }
        }
        g_flag = ok;
    }
}

__global__ void k_convert(const void* eidx) {
    int i = blockIdx.x * 256 + threadIdx.x;
    if (i >= E_) return;
    int s, d;
    if (g_flag) {
        const long long* p = (const long long*)eidx;
        s = (int)p[i]; d = (int)p[E_ + i];
    } else {
        const int* p = (const int*)eidx;
        s = p[i]; d = p[E_ + i];
    }
    g_src[i] = s; g_dst[i] = d;
    atomicAdd(&g_deg[d], 1);
}

#define SCAN_T 1024
__global__ void __launch_bounds__(SCAN_T) k_scan() {
    __shared__ int sums[SCAN_T];
    int t = threadIdx.x;
    const int chunk = (N_ + SCAN_T - 1) / SCAN_T;  // 49
    int lo = t * chunk, hi = min(lo + chunk, N_);
    int s = 0;
    for (int i = lo; i < hi; i++) s += g_deg[i];
    sums[t] = s;
    __syncthreads();
    for (int off = 1; off < SCAN_T; off <<= 1) {
        int v = (t >= off) ? sums[t - off] : 0;
        __syncthreads();
        sums[t] += v;
        __syncthreads();
    }
    int run = sums[t] - s;  // exclusive prefix
    for (int i = lo; i < hi; i++) {
        g_rowstart[i] = run;
        int d = g_deg[i];
        run += d;
        g_dinv[i] = rsqrtf((float)(d + 1));  // +1 self loop
        g_fill[i] = 0;
    }
    if (t == 0) g_rowstart[N_] = E_;
}

__global__ void k_csr() {
    int i = blockIdx.x * 256 + threadIdx.x;
    if (i >= E_) return;
    int d = g_dst[i];
    int pos = g_rowstart[d] + atomicAdd(&g_fill[d], 1);
    g_esrc[pos] = g_src[i];
}

// ------- fp32 GEMM: C[N,CO] = A[N,128] @ W[128,CO]; BM=128 BN=64 TM=8 TN=4 --
__global__ void __launch_bounds__(256) k_gemm(const float* __restrict__ A,
                                              const float* __restrict__ W,
                                              float* __restrict__ C, int CO) {
    __shared__ float As[16][132];  // [k][m] transposed, padded (2-way STS only)
    __shared__ float Bs[16][64];   // [k][n]
    const int bm = blockIdx.x * 128, bn = blockIdx.y * 64;
    const int tid = threadIdx.x, tx = tid & 15, ty = tid >> 4;
    const int ar = tid >> 2, ak = (tid & 3) * 4;   // A-load mapping
    const int bk = tid >> 4, bc = (tid & 15) * 4;  // B-load mapping

    float acc[8][4];
#pragma unroll
    for (int i = 0; i < 8; i++)
#pragma unroll
        for (int j = 0; j < 4; j++) acc[i][j] = 0.f;

    for (int k0 = 0; k0 < 128; k0 += 16) {
#pragma unroll
        for (int half = 0; half < 2; half++) {
            int r = ar + half * 64, gr = bm + r;
            float4 f = make_float4(0.f, 0.f, 0.f, 0.f);
            if (gr < N_) f = *(const float4*)(A + (size_t)gr * 128 + k0 + ak);
            As[ak + 0][r] = f.x; As[ak + 1][r] = f.y;
            As[ak + 2][r] = f.z; As[ak + 3][r] = f.w;
        }
        *(float4*)&Bs[bk][bc] = *(const float4*)(W + (size_t)(k0 + bk) * CO + bn + bc);
        __syncthreads();
#pragma unroll
        for (int kk = 0; kk < 16; kk++) {
            float4 a0 = *(const float4*)&As[kk][ty * 4];        // broadcast
            float4 a1 = *(const float4*)&As[kk][64 + ty * 4];   // broadcast
            float4 b0 = *(const float4*)&Bs[kk][tx * 4];        // conflict-free
            float a[8] = {a0.x, a0.y, a0.z, a0.w, a1.x, a1.y, a1.z, a1.w};
            float b[4] = {b0.x, b0.y, b0.z, b0.w};
#pragma unroll
            for (int i = 0; i < 8; i++)
#pragma unroll
                for (int j = 0; j < 4; j++) acc[i][j] += a[i] * b[j];
        }
        __syncthreads();
    }
#pragma unroll
    for (int i = 0; i < 8; i++) {
        int r = bm + (i < 4 ? ty * 4 + i : 64 + ty * 4 + (i - 4));
        if (r < N_) {
            float4 o = make_float4(acc[i][0], acc[i][1], acc[i][2], acc[i][3]);
            *(float4*)(C + (size_t)r * CO + bn + tx * 4) = o;
        }
    }
}

// ------- GCN aggregate (gather) fused with bias + BN + ReLU -----------------
__global__ void __launch_bounds__(256) k_gcn_gather(
    const float* __restrict__ h, float* __restrict__ out,
    const float* __restrict__ bias, const float* __restrict__ gamma,
    const float* __restrict__ beta, const float* __restrict__ mean,
    const float* __restrict__ var) {
    int n = (blockIdx.x * 256 + threadIdx.x) >> 5;
    if (n >= N_) return;
    int lane = threadIdx.x & 31, c = lane * 4;
    float din = g_dinv[n];
    float ws = din * din;
    float4 acc = *(const float4*)(h + (size_t)n * 128 + c);
    acc.x *= ws; acc.y *= ws; acc.z *= ws; acc.w *= ws;
    int beg = g_rowstart[n], end = g_rowstart[n + 1];
    int j = beg;
    for (; j + 1 < end; j += 2) {  // 2-way for MLP
        int s0 = g_esrc[j], s1 = g_esrc[j + 1];
        float w0 = g_dinv[s0] * din, w1 = g_dinv[s1] * din;
        float4 v0 = *(const float4*)(h + (size_t)s0 * 128 + c);
        float4 v1 = *(const float4*)(h + (size_t)s1 * 128 + c);
        acc.x += w0 * v0.x + w1 * v1.x;
        acc.y += w0 * v0.y + w1 * v1.y;
        acc.z += w0 * v0.z + w1 * v1.z;
        acc.w += w0 * v0.w + w1 * v1.w;
    }
    if (j < end) {
        int s0 = g_esrc[j];
        float w0 = g_dinv[s0] * din;
        float4 v0 = *(const float4*)(h + (size_t)s0 * 128 + c);
        acc.x += w0 * v0.x; acc.y += w0 * v0.y;
        acc.z += w0 * v0.z; acc.w += w0 * v0.w;
    }
    float4 o;
    float* ap = &acc.x; float* op = &o.x;
#pragma unroll
    for (int i = 0; i < 4; i++) {
        int ci = c + i;
        float v = ap[i] + bias[ci];
        v = (v - mean[ci]) * rsqrtf(var[ci] + 1e-5f) * gamma[ci] + beta[ci];
        op[i] = fmaxf(v, 0.f);
    }
    *(float4*)(out + (size_t)n * 128 + c) = o;
}

// ------- GAT attention logits (per node, per head) --------------------------
template <int C>
__global__ void __launch_bounds__(256) k_al(const float* __restrict__ hg,
                                            const float* __restrict__ asrc,
                                            const float* __restrict__ adst) {
    int gw = (blockIdx.x * 256 + threadIdx.x) >> 5;
    int lane = threadIdx.x & 31;
    int n = gw >> 1, h = gw & 1;
    if (n >= N_) return;
    const float* hp = hg + (size_t)n * (2 * C) + h * C;
    float s = 0.f, d = 0.f;
#pragma unroll
    for (int c = lane; c < C; c += 32) {
        float hv = hp[c];
        s += hv * asrc[h * C + c];
        d += hv * adst[h * C + c];
    }
    s = wred_sum(s); d = wred_sum(d);
    if (lane == 0) { g_als[n * 2 + h] = s; g_ald[n * 2 + h] = d; }
}

// ------- GAT aggregate (gather), C=128, fused head-mean + bias + ReLU -------
__global__ void __launch_bounds__(256) k_gat_gather128(
    const float* __restrict__ hg, float* __restrict__ out,
    const float* __restrict__ bias) {
    int n = (blockIdx.x * 256 + threadIdx.x) >> 5;
    if (n >= N_) return;
    int lane = threadIdx.x & 31, c = lane * 4;
    float ald0 = g_ald[n * 2], ald1 = g_ald[n * 2 + 1];
    float e0s = lrelu(g_als[n * 2] + ald0);
    float e1s = lrelu(g_als[n * 2 + 1] + ald1);
    int beg = g_rowstart[n], end = g_rowstart[n + 1];
    float m0 = e0s, m1 = e1s;
    for (int j = beg; j < end; j++) {
        int s = g_esrc[j];
        m0 = fmaxf(m0, lrelu(g_als[s * 2] + ald0));
        m1 = fmaxf(m1, lrelu(g_als[s * 2 + 1] + ald1));
    }
    float den0 = __expf(e0s - m0), den1 = __expf(e1s - m1);
    const float* hn = hg + (size_t)n * 256;
    float4 a0 = *(const float4*)(hn + c);
    float4 a1 = *(const float4*)(hn + 128 + c);
    float4 acc0 = make_float4(den0 * a0.x, den0 * a0.y, den0 * a0.z, den0 * a0.w);
    float4 acc1 = make_float4(den1 * a1.x, den1 * a1.y, den1 * a1.z, den1 * a1.w);
    for (int j = beg; j < end; j++) {
        int s = g_esrc[j];
        float w0 = __expf(lrelu(g_als[s * 2] + ald0) - m0);
        float w1 = __expf(lrelu(g_als[s * 2 + 1] + ald1) - m1);
        den0 += w0; den1 += w1;
        const float* hs = hg + (size_t)s * 256;
        float4 v0 = *(const float4*)(hs + c);
        float4 v1 = *(const float4*)(hs + 128 + c);
        acc0.x += w0 * v0.x; acc0.y += w0 * v0.y;
        acc0.z += w0 * v0.z; acc0.w += w0 * v0.w;
        acc1.x += w1 * v1.x; acc1.y += w1 * v1.y;
        acc1.z += w1 * v1.z; acc1.w += w1 * v1.w;
    }
    float r0 = 0.5f / den0, r1 = 0.5f / den1;
    float4 o;
    o.x = fmaxf(acc0.x * r0 + acc1.x * r1 + bias[c + 0], 0.f);
    o.y = fmaxf(acc0.y * r0 + acc1.y * r1 + bias[c + 1], 0.f);
    o.z = fmaxf(acc0.z * r0 + acc1.z * r1 + bias[c + 2], 0.f);
    o.w = fmaxf(acc0.w * r0 + acc1.w * r1 + bias[c + 3], 0.f);
    *(float4*)(out + (size_t)n * 128 + c) = o;
}

// ------- GAT aggregate, C=64, fused head-mean + bias + log_softmax ----------
__global__ void __launch_bounds__(256) k_gat_gather64(
    const float* __restrict__ hg, float* __restrict__ out,
    const float* __restrict__ bias) {
    int n = (blockIdx.x * 256 + threadIdx.x) >> 5;
    if (n >= N_) return;
    int lane = threadIdx.x & 31;
    int h = lane >> 4, cl = lane & 15, c = cl * 4;
    float ald = g_ald[n * 2 + h];
    float es = lrelu(g_als[n * 2 + h] + ald);
    int beg = g_rowstart[n], end = g_rowstart[n + 1];
    float m = es;
    for (int j = beg; j < end; j++) {
        int s = g_esrc[j];
        m = fmaxf(m, lrelu(g_als[s * 2 + h] + ald));
    }
    float den = __expf(es - m);
    const float* hn = hg + (size_t)n * 128 + h * 64;
    float4 a = *(const float4*)(hn + c);
    float4 acc = make_float4(den * a.x, den * a.y, den * a.z, den * a.w);
    for (int j = beg; j < end; j++) {
        int s = g_esrc[j];
        float w = __expf(lrelu(g_als[s * 2 + h] + ald) - m);
        den += w;
        float4 v = *(const float4*)(hg + (size_t)s * 128 + h * 64 + c);
        acc.x += w * v.x; acc.y += w * v.y;
        acc.z += w * v.z; acc.w += w * v.w;
    }
    float inv = 1.f / den;
    float4 v = make_float4(acc.x * inv, acc.y * inv, acc.z * inv, acc.w * inv);
    // combine heads: lane l pairs with lane l^16 (same channels, other head)
    float4 o;
    o.x = 0.5f * (v.x + __shfl_xor_sync(0xffffffffu, v.x, 16)) + bias[c + 0];
    o.y = 0.5f * (v.y + __shfl_xor_sync(0xffffffffu, v.y, 16)) + bias[c + 1];
    o.z = 0.5f * (v.z + __shfl_xor_sync(0xffffffffu, v.z, 16)) + bias[c + 2];
    o.w = 0.5f * (v.w + __shfl_xor_sync(0xffffffffu, v.w, 16)) + bias[c + 3];
    // o is identical on lane l and l^16 -> reductions within 16-lane xor-groups
    float lm = fmaxf(fmaxf(o.x, o.y), fmaxf(o.z, o.w));
#pragma unroll
    for (int off = 8; off; off >>= 1) lm = fmaxf(lm, __shfl_xor_sync(0xffffffffu, lm, off));
    float sum = __expf(o.x - lm) + __expf(o.y - lm) + __expf(o.z - lm) + __expf(o.w - lm);
#pragma unroll
    for (int off = 8; off; off >>= 1) sum += __shfl_xor_sync(0xffffffffu, sum, off);
    float l = lm + logf(sum);
    if (lane < 16) {
        float4 r = make_float4(o.x - l, o.y - l, o.z - l, o.w - l);
        *(float4*)(out + (size_t)n * 64 + c) = r;
    }
}

// ---------------- launch -----------------------------------------------------
extern "C" void kernel_launch(void* const* d_in, const int* in_sizes, int n_in,
                              void* d_out, int out_size) {
    const float* x   = (const float*)d_in[0];
    const void*  ei  = d_in[1];
    const float* Wg1 = (const float*)d_in[2];
    const float* bg1 = (const float*)d_in[3];
    const float* g1g = (const float*)d_in[4];
    const float* g1b = (const float*)d_in[5];
    const float* g1m = (const float*)d_in[6];
    const float* g1v = (const float*)d_in[7];
    const float* Wa1 = (const float*)d_in[8];
    const float* as1 = (const float*)d_in[9];
    const float* ad1 = (const float*)d_in[10];
    const float* ba1 = (const float*)d_in[11];
    const float* Wg2 = (const float*)d_in[12];
    const float* bg2 = (const float*)d_in[13];
    const float* g2g = (const float*)d_in[14];
    const float* g2b = (const float*)d_in[15];
    const float* g2m = (const float*)d_in[16];
    const float* g2v = (const float*)d_in[17];
    const float* Wa2 = (const float*)d_in[18];
    const float* as2 = (const float*)d_in[19];
    const float* ad2 = (const float*)d_in[20];
    const float* ba2 = (const float*)d_in[21];
    float* out = (float*)d_out;

    float *bufA, *bufC;
    cudaGetSymbolAddress((void**)&bufA, g_bufA);
    cudaGetSymbolAddress((void**)&bufC, g_bufC);

    const int TB = 256;
    const int nb = (N_ + TB - 1) / TB;       // node-parallel (thread per node)
    const int eb = (E_ + TB - 1) / TB;       // edge-parallel (thread per edge)
    const int nw = (N_ * 32 + TB - 1) / TB;  // warp per node
    const int aw = (2 * N_ * 32 + TB - 1) / TB;  // warp per (node, head)
    const int GX = (N_ + 127) / 128;         // 391 GEMM row tiles

    // ---- preprocessing: dtype detect, deg, CSR build
    k_prep<<<nb, TB>>>(ei);
    k_convert<<<eb, TB>>>(ei);
    k_scan<<<1, SCAN_T>>>();
    k_csr<<<eb, TB>>>();

    // ---- GCN1 (+ bias + BN1 + ReLU fused into gather)
    k_gemm<<<dim3(GX, 2), TB>>>(x, Wg1, bufA, 128);
    k_gcn_gather<<<nw, TB>>>(bufA, bufC, bg1, g1g, g1b, g1m, g1v);

    // ---- GAT1 (+ head-mean + bias + ReLU fused)
    k_gemm<<<dim3(GX, 4), TB>>>(bufC, Wa1, bufA, 256);
    k_al<128><<<aw, TB>>>(bufA, as1, ad1);
    k_gat_gather128<<<nw, TB>>>(bufA, bufC, ba1);

    // ---- GCN2 (+ bias + BN2 + ReLU fused)
    k_gemm<<<dim3(GX, 2), TB>>>(bufC, Wg2, bufA, 128);
    k_gcn_gather<<<nw, TB>>>(bufA, bufC, bg2, g2g, g2b, g2m, g2v);

    // ---- GAT2 (+ head-mean + bias + log_softmax fused)
    k_gemm<<<dim3(GX, 2), TB>>>(bufC, Wa2, bufA, 128);
    k_al<64><<<aw, TB>>>(bufA, as2, ad2);
    k_gat_gather64<<<nw, TB>>>(bufA, out, ba2);
}

// round 7
// speedup vs baseline: 1.8714x; 1.2366x over previous
#include <cuda_runtime.h>
#include <cuda_fp16.h>
#include <math.h>
#include <stddef.h>

#define N_ 50000
#define E_ 600000
#define SB 200     // scan blocks
#define NPB 250    // nodes per scan block (200*250 = 50000)

// ---------------- device scratch (no allocations allowed) -------------------
__device__ int      g_src[E_];
__device__ int      g_dst[E_];
__device__ int      g_esrc[E_];         // CSR: src ids grouped by dst
__device__ int      g_rowstart[N_ + 1]; // CSR offsets
__device__ int      g_deg[N_];
__device__ int      g_fill[N_];
__device__ int      g_bsum[SB];
__device__ int      g_bpre[SB];
__device__ float    g_dinv[N_];
__device__ int      g_flag;             // 1 = edge_index is int64, 0 = int32
__device__ float    g_als[N_ * 2];
__device__ float    g_ald[N_ * 2];
__device__ float    g_bufA[N_ * 256];   // GEMM outputs fp32 (max width 256)
__device__ __half   g_bufAh[N_ * 256];  // GEMM outputs fp16 (gather feed)
__device__ float    g_bufC[N_ * 128];   // activations between stages

// ---------------- helpers ---------------------------------------------------
__device__ __forceinline__ float lrelu(float e) { return e > 0.f ? e : 0.2f * e; }

__device__ __forceinline__ float wred_sum(float v) {
#pragma unroll
    for (int o = 16; o; o >>= 1) v += __shfl_xor_sync(0xffffffffu, v, o);
    return v;
}

__device__ __forceinline__ float4 ld_h4(const __half* p) {  // 4 halves -> float4
    uint2 u = *(const uint2*)p;
    __half2 h0 = *(__half2*)&u.x, h1 = *(__half2*)&u.y;
    float2 f0 = __half22float2(h0), f1 = __half22float2(h1);
    return make_float4(f0.x, f0.y, f1.x, f1.y);
}
__device__ __forceinline__ uint2 f4_to_h4(float4 v) {
    __half2 h0 = __floats2half2_rn(v.x, v.y);
    __half2 h1 = __floats2half2_rn(v.z, v.w);
    uint2 u;
    u.x = *(unsigned*)&h0; u.y = *(unsigned*)&h1;
    return u;
}

// ---------------- preprocessing ---------------------------------------------
__global__ void k_prep(const void* eidx) {
    int i = blockIdx.x * 256 + threadIdx.x;
    if (i < N_) g_deg[i] = 0;
    if (i == 0) {
        const long long* p = (const long long*)eidx;
        int ok = 1;
        for (int j = 0; j < 128; j++) {
            long long v = p[j];
            if (v < 0 || v >= N_) { ok = 0; break; }
        }
        g_flag = ok;
    }
}

__global__ void k_convert(const void* eidx) {
    int i = blockIdx.x * 256 + threadIdx.x;
    if (i >= E_) return;
    int s, d;
    if (g_flag) {
        const long long* p = (const long long*)eidx;
        s = (int)p[i]; d = (int)p[E_ + i];
    } else {
        const int* p = (const int*)eidx;
        s = p[i]; d = p[E_ + i];
    }
    g_src[i] = s; g_dst[i] = d;
    atomicAdd(&g_deg[d], 1);
}

__global__ void __launch_bounds__(256) k_scan1() {
    __shared__ int sh[256];
    int t = threadIdx.x, b = blockIdx.x;
    int i = b * NPB + t;
    sh[t] = (t < NPB) ? g_deg[i] : 0;
    __syncthreads();
    for (int off = 128; off; off >>= 1) {
        if (t < off) sh[t] += sh[t + off];
        __syncthreads();
    }
    if (t == 0) g_bsum[b] = sh[0];
}

__global__ void __launch_bounds__(256) k_scan2() {
    __shared__ int sh[256];
    int t = threadIdx.x;
    int v = (t < SB) ? g_bsum[t] : 0;
    sh[t] = v;
    __syncthreads();
    for (int off = 1; off < 256; off <<= 1) {
        int u = (t >= off) ? sh[t - off] : 0;
        __syncthreads();
        sh[t] += u;
        __syncthreads();
    }
    if (t < SB) g_bpre[t] = sh[t] - v;  // exclusive
}

__global__ void __launch_bounds__(256) k_scan3() {
    __shared__ int sh[256];
    int t = threadIdx.x, b = blockIdx.x;
    int i = b * NPB + t;
    int d = (t < NPB) ? g_deg[i] : 0;
    sh[t] = d;
    __syncthreads();
    for (int off = 1; off < 256; off <<= 1) {
        int u = (t >= off) ? sh[t - off] : 0;
        __syncthreads();
        sh[t] += u;
        __syncthreads();
    }
    if (t < NPB) {
        g_rowstart[i] = g_bpre[b] + sh[t] - d;
        g_dinv[i] = rsqrtf((float)(d + 1));  // +1 self loop
        g_fill[i] = 0;
    }
    if (b == SB - 1 && t == 0) g_rowstart[N_] = E_;
}

__global__ void k_csr() {
    int i = blockIdx.x * 256 + threadIdx.x;
    if (i >= E_) return;
    int d = g_dst[i];
    int pos = g_rowstart[d] + atomicAdd(&g_fill[d], 1);
    g_esrc[pos] = g_src[i];
}

// ------ fp32 GEMM: C[N,CO] = A[N,128] @ W[128,CO]; BM=128 BN=128 TM=8 TN=8 --
// also emits fp16 copy Ch for the downstream gather kernels
__global__ void __launch_bounds__(256) k_gemm(const float* __restrict__ A,
                                              const float* __restrict__ W,
                                              float* __restrict__ C,
                                              __half* __restrict__ Ch, int CO) {
    __shared__ float As[16][132];  // [k][m] transposed, padded
    __shared__ float Bs[16][128];  // [k][n]
    const int bm = blockIdx.x * 128, bn = blockIdx.y * 128;
    const int tid = threadIdx.x, tx = tid & 15, ty = tid >> 4;

    float acc[8][8];
#pragma unroll
    for (int i = 0; i < 8; i++)
#pragma unroll
        for (int j = 0; j < 8; j++) acc[i][j] = 0.f;

    for (int k0 = 0; k0 < 128; k0 += 16) {
        // load A tile: 512 float4, 2 per thread
#pragma unroll
        for (int v = 0; v < 2; v++) {
            int idx = tid + 256 * v;
            int r = idx >> 2, kq = (idx & 3) * 4;
            int gr = bm + r;
            float4 f = make_float4(0.f, 0.f, 0.f, 0.f);
            if (gr < N_) f = *(const float4*)(A + (size_t)gr * 128 + k0 + kq);
            As[kq + 0][r] = f.x; As[kq + 1][r] = f.y;
            As[kq + 2][r] = f.z; As[kq + 3][r] = f.w;
        }
        // load B tile: 512 float4, 2 per thread
#pragma unroll
        for (int v = 0; v < 2; v++) {
            int idx = tid + 256 * v;
            int bk = idx >> 5, bc = (idx & 31) * 4;
            *(float4*)&Bs[bk][bc] = *(const float4*)(W + (size_t)(k0 + bk) * CO + bn + bc);
        }
        __syncthreads();
#pragma unroll
        for (int kk = 0; kk < 16; kk++) {
            float4 a0 = *(const float4*)&As[kk][ty * 4];       // broadcast
            float4 a1 = *(const float4*)&As[kk][64 + ty * 4];  // broadcast
            float4 b0 = *(const float4*)&Bs[kk][tx * 4];       // conflict-free
            float4 b1 = *(const float4*)&Bs[kk][64 + tx * 4];  // conflict-free
            float a[8] = {a0.x, a0.y, a0.z, a0.w, a1.x, a1.y, a1.z, a1.w};
            float b[8] = {b0.x, b0.y, b0.z, b0.w, b1.x, b1.y, b1.z, b1.w};
#pragma unroll
            for (int i = 0; i < 8; i++)
#pragma unroll
                for (int j = 0; j < 8; j++) acc[i][j] += a[i] * b[j];
        }
        __syncthreads();
    }
#pragma unroll
    for (int i = 0; i < 8; i++) {
        int r = bm + (i < 4 ? ty * 4 + i : 64 + ty * 4 + (i - 4));
        if (r < N_) {
            float4 o0 = make_float4(acc[i][0], acc[i][1], acc[i][2], acc[i][3]);
            float4 o1 = make_float4(acc[i][4], acc[i][5], acc[i][6], acc[i][7]);
            *(float4*)(C + (size_t)r * CO + bn + tx * 4) = o0;
            *(float4*)(C + (size_t)r * CO + bn + 64 + tx * 4) = o1;
            *(uint2*)(Ch + (size_t)r * CO + bn + tx * 4) = f4_to_h4(o0);
            *(uint2*)(Ch + (size_t)r * CO + bn + 64 + tx * 4) = f4_to_h4(o1);
        }
    }
}

// ------- GCN aggregate (gather, fp16 neighbors) + bias + BN + ReLU ----------
__global__ void __launch_bounds__(256) k_gcn_gather(
    const float* __restrict__ h, const __half* __restrict__ hh,
    float* __restrict__ out,
    const float* __restrict__ bias, const float* __restrict__ gamma,
    const float* __restrict__ beta, const float* __restrict__ mean,
    const float* __restrict__ var) {
    int n = (blockIdx.x * 256 + threadIdx.x) >> 5;
    if (n >= N_) return;
    int lane = threadIdx.x & 31, c = lane * 4;
    float din = g_dinv[n];
    float ws = din * din;
    float4 acc = *(const float4*)(h + (size_t)n * 128 + c);  // fp32 self
    acc.x *= ws; acc.y *= ws; acc.z *= ws; acc.w *= ws;
    int beg = g_rowstart[n], end = g_rowstart[n + 1];
    int j = beg;
    for (; j + 1 < end; j += 2) {
        int s0 = g_esrc[j], s1 = g_esrc[j + 1];
        float w0 = g_dinv[s0] * din, w1 = g_dinv[s1] * din;
        float4 v0 = ld_h4(hh + (size_t)s0 * 128 + c);
        float4 v1 = ld_h4(hh + (size_t)s1 * 128 + c);
        acc.x += w0 * v0.x + w1 * v1.x;
        acc.y += w0 * v0.y + w1 * v1.y;
        acc.z += w0 * v0.z + w1 * v1.z;
        acc.w += w0 * v0.w + w1 * v1.w;
    }
    if (j < end) {
        int s0 = g_esrc[j];
        float w0 = g_dinv[s0] * din;
        float4 v0 = ld_h4(hh + (size_t)s0 * 128 + c);
        acc.x += w0 * v0.x; acc.y += w0 * v0.y;
        acc.z += w0 * v0.z; acc.w += w0 * v0.w;
    }
    float4 o;
    float* ap = &acc.x; float* op = &o.x;
#pragma unroll
    for (int i = 0; i < 4; i++) {
        int ci = c + i;
        float v = ap[i] + bias[ci];
        v = (v - mean[ci]) * rsqrtf(var[ci] + 1e-5f) * gamma[ci] + beta[ci];
        op[i] = fmaxf(v, 0.f);
    }
    *(float4*)(out + (size_t)n * 128 + c) = o;
}

// ------- GAT attention logits (per node, per head), fp32 inputs -------------
template <int C>
__global__ void __launch_bounds__(256) k_al(const float* __restrict__ hg,
                                            const float* __restrict__ asrc,
                                            const float* __restrict__ adst) {
    int gw = (blockIdx.x * 256 + threadIdx.x) >> 5;
    int lane = threadIdx.x & 31;
    int n = gw >> 1, h = gw & 1;
    if (n >= N_) return;
    const float* hp = hg + (size_t)n * (2 * C) + h * C;
    float s = 0.f, d = 0.f;
#pragma unroll
    for (int c = lane; c < C; c += 32) {
        float hv = hp[c];
        s += hv * asrc[h * C + c];
        d += hv * adst[h * C + c];
    }
    s = wred_sum(s); d = wred_sum(d);
    if (lane == 0) { g_als[n * 2 + h] = s; g_ald[n * 2 + h] = d; }
}

// ------- GAT aggregate (fp16 neighbors), C=128, + head-mean + bias + ReLU ---
__global__ void __launch_bounds__(256) k_gat_gather128(
    const float* __restrict__ hg, const __half* __restrict__ hgh,
    float* __restrict__ out, const float* __restrict__ bias) {
    int n = (blockIdx.x * 256 + threadIdx.x) >> 5;
    if (n >= N_) return;
    int lane = threadIdx.x & 31, c = lane * 4;
    float ald0 = g_ald[n * 2], ald1 = g_ald[n * 2 + 1];
    float e0s = lrelu(g_als[n * 2] + ald0);
    float e1s = lrelu(g_als[n * 2 + 1] + ald1);
    int beg = g_rowstart[n], end = g_rowstart[n + 1];
    float m0 = e0s, m1 = e1s;
    for (int j = beg; j < end; j++) {
        int s = g_esrc[j];
        m0 = fmaxf(m0, lrelu(g_als[s * 2] + ald0));
        m1 = fmaxf(m1, lrelu(g_als[s * 2 + 1] + ald1));
    }
    float den0 = __expf(e0s - m0), den1 = __expf(e1s - m1);
    const float* hn = hg + (size_t)n * 256;  // fp32 self
    float4 a0 = *(const float4*)(hn + c);
    float4 a1 = *(const float4*)(hn + 128 + c);
    float4 acc0 = make_float4(den0 * a0.x, den0 * a0.y, den0 * a0.z, den0 * a0.w);
    float4 acc1 = make_float4(den1 * a1.x, den1 * a1.y, den1 * a1.z, den1 * a1.w);
    for (int j = beg; j < end; j++) {
        int s = g_esrc[j];
        float w0 = __expf(lrelu(g_als[s * 2] + ald0) - m0);
        float w1 = __expf(lrelu(g_als[s * 2 + 1] + ald1) - m1);
        den0 += w0; den1 += w1;
        const __half* hs = hgh + (size_t)s * 256;
        float4 v0 = ld_h4(hs + c);
        float4 v1 = ld_h4(hs + 128 + c);
        acc0.x += w0 * v0.x; acc0.y += w0 * v0.y;
        acc0.z += w0 * v0.z; acc0.w += w0 * v0.w;
        acc1.x += w1 * v1.x; acc1.y += w1 * v1.y;
        acc1.z += w1 * v1.z; acc1.w += w1 * v1.w;
    }
    float r0 = 0.5f / den0, r1 = 0.5f / den1;
    float4 o;
    o.x = fmaxf(acc0.x * r0 + acc1.x * r1 + bias[c + 0], 0.f);
    o.y = fmaxf(acc0.y * r0 + acc1.y * r1 + bias[c + 1], 0.f);
    o.z = fmaxf(acc0.z * r0 + acc1.z * r1 + bias[c + 2], 0.f);
    o.w = fmaxf(acc0.w * r0 + acc1.w * r1 + bias[c + 3], 0.f);
    *(float4*)(out + (size_t)n * 128 + c) = o;
}

// ------- GAT aggregate (fp16), C=64, + head-mean + bias + log_softmax -------
__global__ void __launch_bounds__(256) k_gat_gather64(
    const float* __restrict__ hg, const __half* __restrict__ hgh,
    float* __restrict__ out, const float* __restrict__ bias) {
    int n = (blockIdx.x * 256 + threadIdx.x) >> 5;
    if (n >= N_) return;
    int lane = threadIdx.x & 31;
    int h = lane >> 4, cl = lane & 15, c = cl * 4;
    float ald = g_ald[n * 2 + h];
    float es = lrelu(g_als[n * 2 + h] + ald);
    int beg = g_rowstart[n], end = g_rowstart[n + 1];
    float m = es;
    for (int j = beg; j < end; j++) {
        int s = g_esrc[j];
        m = fmaxf(m, lrelu(g_als[s * 2 + h] + ald));
    }
    float den = __expf(es - m);
    const float* hn = hg + (size_t)n * 128 + h * 64;  // fp32 self
    float4 a = *(const float4*)(hn + c);
    float4 acc = make_float4(den * a.x, den * a.y, den * a.z, den * a.w);
    for (int j = beg; j < end; j++) {
        int s = g_esrc[j];
        float w = __expf(lrelu(g_als[s * 2 + h] + ald) - m);
        den += w;
        float4 v = ld_h4(hgh + (size_t)s * 128 + h * 64 + c);
        acc.x += w * v.x; acc.y += w * v.y;
        acc.z += w * v.z; acc.w += w * v.w;
    }
    float inv = 1.f / den;
    float4 v = make_float4(acc.x * inv, acc.y * inv, acc.z * inv, acc.w * inv);
    float4 o;
    o.x = 0.5f * (v.x + __shfl_xor_sync(0xffffffffu, v.x, 16)) + bias[c + 0];
    o.y = 0.5f * (v.y + __shfl_xor_sync(0xffffffffu, v.y, 16)) + bias[c + 1];
    o.z = 0.5f * (v.z + __shfl_xor_sync(0xffffffffu, v.z, 16)) + bias[c + 2];
    o.w = 0.5f * (v.w + __shfl_xor_sync(0xffffffffu, v.w, 16)) + bias[c + 3];
    float lm = fmaxf(fmaxf(o.x, o.y), fmaxf(o.z, o.w));
#pragma unroll
    for (int off = 8; off; off >>= 1) lm = fmaxf(lm, __shfl_xor_sync(0xffffffffu, lm, off));
    float sum = __expf(o.x - lm) + __expf(o.y - lm) + __expf(o.z - lm) + __expf(o.w - lm);
#pragma unroll
    for (int off = 8; off; off >>= 1) sum += __shfl_xor_sync(0xffffffffu, sum, off);
    float l = lm + logf(sum);
    if (lane < 16) {
        float4 r = make_float4(o.x - l, o.y - l, o.z - l, o.w - l);
        *(float4*)(out + (size_t)n * 64 + c) = r;
    }
}

// ---------------- launch -----------------------------------------------------
extern "C" void kernel_launch(void* const* d_in, const int* in_sizes, int n_in,
                              void* d_out, int out_size) {
    const float* x   = (const float*)d_in[0];
    const void*  ei  = d_in[1];
    const float* Wg1 = (const float*)d_in[2];
    const float* bg1 = (const float*)d_in[3];
    const float* g1g = (const float*)d_in[4];
    const float* g1b = (const float*)d_in[5];
    const float* g1m = (const float*)d_in[6];
    const float* g1v = (const float*)d_in[7];
    const float* Wa1 = (const float*)d_in[8];
    const float* as1 = (const float*)d_in[9];
    const float* ad1 = (const float*)d_in[10];
    const float* ba1 = (const float*)d_in[11];
    const float* Wg2 = (const float*)d_in[12];
    const float* bg2 = (const float*)d_in[13];
    const float* g2g = (const float*)d_in[14];
    const float* g2b = (const float*)d_in[15];
    const float* g2m = (const float*)d_in[16];
    const float* g2v = (const float*)d_in[17];
    const float* Wa2 = (const float*)d_in[18];
    const float* as2 = (const float*)d_in[19];
    const float* ad2 = (const float*)d_in[20];
    const float* ba2 = (const float*)d_in[21];
    float* out = (float*)d_out;

    float *bufA, *bufC;
    __half* bufAh;
    cudaGetSymbolAddress((void**)&bufA, g_bufA);
    cudaGetSymbolAddress((void**)&bufAh, g_bufAh);
    cudaGetSymbolAddress((void**)&bufC, g_bufC);

    const int TB = 256;
    const int nb = (N_ + TB - 1) / TB;
    const int eb = (E_ + TB - 1) / TB;
    const int nw = (N_ * 32 + TB - 1) / TB;       // warp per node
    const int aw = (2 * N_ * 32 + TB - 1) / TB;   // warp per (node, head)
    const int GX = (N_ + 127) / 128;              // 391 GEMM row tiles

    // ---- preprocessing: dtype detect, deg, CSR build (parallel scan)
    k_prep<<<nb, TB>>>(ei);
    k_convert<<<eb, TB>>>(ei);
    k_scan1<<<SB, TB>>>();
    k_scan2<<<1, TB>>>();
    k_scan3<<<SB, TB>>>();
    k_csr<<<eb, TB>>>();

    // ---- GCN1 (+ bias + BN1 + ReLU fused into gather)
    k_gemm<<<dim3(GX, 1), TB>>>(x, Wg1, bufA, bufAh, 128);
    k_gcn_gather<<<nw, TB>>>(bufA, bufAh, bufC, bg1, g1g, g1b, g1m, g1v);

    // ---- GAT1 (+ head-mean + bias + ReLU fused)
    k_gemm<<<dim3(GX, 2), TB>>>(bufC, Wa1, bufA, bufAh, 256);
    k_al<128><<<aw, TB>>>(bufA, as1, ad1);
    k_gat_gather128<<<nw, TB>>>(bufA, bufAh, bufC, ba1);

    // ---- GCN2 (+ bias + BN2 + ReLU fused)
    k_gemm<<<dim3(GX, 1), TB>>>(bufC, Wg2, bufA, bufAh, 128);
    k_gcn_gather<<<nw, TB>>>(bufA, bufAh, bufC, bg2, g2g, g2b, g2m, g2v);

    // ---- GAT2 (+ head-mean + bias + log_softmax fused)
    k_gemm<<<dim3(GX, 1), TB>>>(bufC, Wa2, bufA, bufAh, 128);
    k_al<64><<<aw, TB>>>(bufA, as2, ad2);
    k_gat_gather64<<<nw, TB>>>(bufA, bufAh, out, ba2);
}

// round 8
// speedup vs baseline: 2.2940x; 1.2259x over previous
#include <cuda_runtime.h>
#include <cuda_fp16.h>
#include <math.h>
#include <stddef.h>
#include <stdint.h>

#define N_ 50000
#define E_ 600000
#define SB 200     // scan blocks
#define NPB 250    // nodes per scan block (200*250 = 50000)

// ---------------- device scratch (no allocations allowed) -------------------
__device__ int      g_src[E_];
__device__ int      g_dst[E_];
__device__ int      g_esrc[E_];         // CSR: src ids grouped by dst
__device__ int      g_rowstart[N_ + 1]; // CSR offsets
__device__ int      g_deg[N_];
__device__ int      g_fill[N_];
__device__ int      g_bsum[SB];
__device__ int      g_bpre[SB];
__device__ float    g_dinv[N_];
__device__ int      g_flag;             // 1 = edge_index is int64, 0 = int32
__device__ float    g_als[N_ * 2];
__device__ float    g_ald[N_ * 2];
__device__ float    g_va[4 * 128];      // folded attention projections W@a
__device__ __half   g_wt[256 * 128];    // transposed fp16 weights [CO][128]
__device__ __half   g_xh[N_ * 128];     // fp16 copy of input x
__device__ float    g_bufA[N_ * 256];   // GEMM outputs fp32 (max width 256)
__device__ __half   g_bufAh[N_ * 256];  // GEMM outputs fp16 (gather feed)
__device__ float    g_bufC[N_ * 128];   // activations fp32
__device__ __half   g_bufCh[N_ * 128];  // activations fp16 (GEMM feed)

// ---------------- helpers ---------------------------------------------------
__device__ __forceinline__ float lrelu(float e) { return e > 0.f ? e : 0.2f * e; }

__device__ __forceinline__ float wred_sum(float v) {
#pragma unroll
    for (int o = 16; o; o >>= 1) v += __shfl_xor_sync(0xffffffffu, v, o);
    return v;
}

__device__ __forceinline__ float4 ld_h4(const __half* p) {
    uint2 u = *(const uint2*)p;
    __half2 h0 = *(__half2*)&u.x, h1 = *(__half2*)&u.y;
    float2 f0 = __half22float2(h0), f1 = __half22float2(h1);
    return make_float4(f0.x, f0.y, f1.x, f1.y);
}
__device__ __forceinline__ uint2 f4_to_h4(float4 v) {
    __half2 h0 = __floats2half2_rn(v.x, v.y);
    __half2 h1 = __floats2half2_rn(v.z, v.w);
    uint2 u;
    u.x = *(unsigned*)&h0; u.y = *(unsigned*)&h1;
    return u;
}
__device__ __forceinline__ uint32_t smem_u32(const void* p) {
    return (uint32_t)__cvta_generic_to_shared(p);
}
__device__ __forceinline__ void ldm4(uint32_t& r0, uint32_t& r1, uint32_t& r2,
                                     uint32_t& r3, uint32_t addr) {
    asm volatile("ldmatrix.sync.aligned.m8n8.x4.shared.b16 {%0,%1,%2,%3}, [%4];"
                 : "=r"(r0), "=r"(r1), "=r"(r2), "=r"(r3) : "r"(addr));
}
__device__ __forceinline__ void mma16816(float* d, const uint32_t* a,
                                         uint32_t b0, uint32_t b1) {
    asm volatile(
        "mma.sync.aligned.m16n8k16.row.col.f32.f16.f16.f32 "
        "{%0,%1,%2,%3}, {%4,%5,%6,%7}, {%8,%9}, {%0,%1,%2,%3};"
        : "+f"(d[0]), "+f"(d[1]), "+f"(d[2]), "+f"(d[3])
        : "r"(a[0]), "r"(a[1]), "r"(a[2]), "r"(a[3]), "r"(b0), "r"(b1));
}

// ---------------- preprocessing ---------------------------------------------
__global__ void k_prep(const void* eidx) {
    int i = blockIdx.x * 256 + threadIdx.x;
    if (i < N_) g_deg[i] = 0;
    if (i == 0) {
        const long long* p = (const long long*)eidx;
        int ok = 1;
        for (int j = 0; j < 128; j++) {
            long long v = p[j];
            if (v < 0 || v >= N_) { ok = 0; break; }
        }
        g_flag = ok;
    }
}

__global__ void k_convert(const void* eidx) {
    int i = blockIdx.x * 256 + threadIdx.x;
    if (i >= E_) return;
    int s, d;
    if (g_flag) {
        const long long* p = (const long long*)eidx;
        s = (int)p[i]; d = (int)p[E_ + i];
    } else {
        const int* p = (const int*)eidx;
        s = p[i]; d = p[E_ + i];
    }
    g_src[i] = s; g_dst[i] = d;
    atomicAdd(&g_deg[d], 1);
}

__global__ void __launch_bounds__(256) k_scan1() {
    __shared__ int sh[256];
    int t = threadIdx.x, b = blockIdx.x;
    int i = b * NPB + t;
    sh[t] = (t < NPB) ? g_deg[i] : 0;
    __syncthreads();
    for (int off = 128; off; off >>= 1) {
        if (t < off) sh[t] += sh[t + off];
        __syncthreads();
    }
    if (t == 0) g_bsum[b] = sh[0];
}

__global__ void __launch_bounds__(256) k_scan2() {
    __shared__ int sh[256];
    int t = threadIdx.x;
    int v = (t < SB) ? g_bsum[t] : 0;
    sh[t] = v;
    __syncthreads();
    for (int off = 1; off < 256; off <<= 1) {
        int u = (t >= off) ? sh[t - off] : 0;
        __syncthreads();
        sh[t] += u;
        __syncthreads();
    }
    if (t < SB) g_bpre[t] = sh[t] - v;  // exclusive
}

__global__ void __launch_bounds__(256) k_scan3() {
    __shared__ int sh[256];
    int t = threadIdx.x, b = blockIdx.x;
    int i = b * NPB + t;
    int d = (t < NPB) ? g_deg[i] : 0;
    sh[t] = d;
    __syncthreads();
    for (int off = 1; off < 256; off <<= 1) {
        int u = (t >= off) ? sh[t - off] : 0;
        __syncthreads();
        sh[t] += u;
        __syncthreads();
    }
    if (t < NPB) {
        g_rowstart[i] = g_bpre[b] + sh[t] - d;
        g_dinv[i] = rsqrtf((float)(d + 1));  // +1 self loop
        g_fill[i] = 0;
    }
    if (b == SB - 1 && t == 0) g_rowstart[N_] = E_;
}

__global__ void k_csr() {
    int i = blockIdx.x * 256 + threadIdx.x;
    if (i >= E_) return;
    int d = g_dst[i];
    int pos = g_rowstart[d] + atomicAdd(&g_fill[d], 1);
    g_esrc[pos] = g_src[i];
}

// ---------------- conversions -----------------------------------------------
__global__ void k_x2h(const float* __restrict__ x, __half* __restrict__ xh) {
    int i = blockIdx.x * 256 + threadIdx.x;
    if (i < N_ * 32) {
        float4 v = *(const float4*)(x + (size_t)i * 4);
        *(uint2*)(xh + (size_t)i * 4) = f4_to_h4(v);
    }
}

// W [128, CO] fp32 -> Wt [CO][128] fp16 (transposed, K-contiguous)
__global__ void k_wcvt(const float* __restrict__ W, __half* __restrict__ Wt, int CO) {
    int idx = blockIdx.x * 256 + threadIdx.x;
    if (idx >= CO * 128) return;
    int n = idx >> 7, k = idx & 127;
    Wt[idx] = __float2half(W[(size_t)k * CO + n]);
}

// va[j][k] = sum_c W[k][h*C + c] * a[h][c]; j: 0,1=src h0,h1; 2,3=dst h0,h1
__global__ void k_va(const float* __restrict__ W, const float* __restrict__ asrc,
                     const float* __restrict__ adst, int CO, int C) {
    int j = blockIdx.x, k = threadIdx.x;
    const float* a = (j < 2) ? asrc : adst;
    int h = j & 1;
    float s = 0.f;
    for (int c = 0; c < C; c++) s += W[(size_t)k * CO + h * C + c] * a[h * C + c];
    g_va[j * 128 + k] = s;
}

// attention logits from GEMM *input* (fp16): al = x @ va
__global__ void __launch_bounds__(256) k_alv(const __half* __restrict__ Ah) {
    __shared__ float vs[4][128];
    int tid = threadIdx.x;
    for (int i = tid; i < 512; i += 256) vs[i >> 7][i & 127] = g_va[i];
    __syncthreads();
    int n = (blockIdx.x * 256 + tid) >> 5;
    if (n >= N_) return;
    int lane = tid & 31, c = lane * 4;
    float4 v = ld_h4(Ah + (size_t)n * 128 + c);
    float r[4];
#pragma unroll
    for (int j = 0; j < 4; j++) {
        float s = v.x * vs[j][c] + v.y * vs[j][c + 1] +
                  v.z * vs[j][c + 2] + v.w * vs[j][c + 3];
        r[j] = wred_sum(s);
    }
    if (lane == 0) {
        g_als[n * 2 + 0] = r[0]; g_als[n * 2 + 1] = r[1];
        g_ald[n * 2 + 0] = r[2]; g_ald[n * 2 + 1] = r[3];
    }
}

// ---- HMMA GEMM: C[N,CO] = A[N,128](fp16) @ Wt[CO,128](fp16)^T --------------
// BM=128, BN=64, full K=128 resident. XOR-swizzled smem, ldmatrix, m16n8k16.
__global__ void __launch_bounds__(256) k_gemm_h(const __half* __restrict__ A,
                                                const __half* __restrict__ Wt,
                                                float* __restrict__ C,
                                                __half* __restrict__ Ch, int CO) {
    __shared__ __half As[128 * 128];  // row r: granule g stored at (g ^ (r&7))
    __shared__ __half Bs[64 * 128];
    const int bm = blockIdx.x * 128, bn = blockIdx.y * 64;
    const int tid = threadIdx.x;
    const int warp = tid >> 5, lane = tid & 31;

    // load A tile (rows bm..bm+127, all K)
    {
        int r = tid >> 1, hh = tid & 1;
        int gr = bm + r;
        const uint4* src = (const uint4*)(A + (size_t)gr * 128 + hh * 64);
        uint4 z = make_uint4(0, 0, 0, 0);
#pragma unroll
        for (int g = 0; g < 8; g++) {
            int gg = hh * 8 + g;
            uint4 v = (gr < N_) ? src[g] : z;
            *(uint4*)&As[r * 128 + ((gg ^ (r & 7)) << 3)] = v;
        }
    }
    // load B tile (Wt rows bn..bn+63, all K)
    {
        int n = tid >> 2, q = tid & 3;
        const uint4* src = (const uint4*)(Wt + (size_t)(bn + n) * 128 + q * 32);
#pragma unroll
        for (int g = 0; g < 4; g++) {
            int gg = q * 4 + g;
            uint4 v = src[g];
            *(uint4*)&Bs[n * 128 + ((gg ^ (n & 7)) << 3)] = v;
        }
    }
    __syncthreads();

    const uint32_t sA = smem_u32(As), sB = smem_u32(Bs);
    const int wm = (warp & 3) * 32, wn = (warp >> 2) * 32;
    float acc[2][4][4];
#pragma unroll
    for (int mt = 0; mt < 2; mt++)
#pragma unroll
        for (int nt = 0; nt < 4; nt++)
#pragma unroll
            for (int i = 0; i < 4; i++) acc[mt][nt][i] = 0.f;

#pragma unroll
    for (int kk = 0; kk < 8; kk++) {
        uint32_t a[2][4];
#pragma unroll
        for (int mt = 0; mt < 2; mt++) {
            int r = wm + mt * 16 + (lane & 15);
            int kg = kk * 2 + (lane >> 4);
            ldm4(a[mt][0], a[mt][1], a[mt][2], a[mt][3],
                 sA + (uint32_t)(r * 128 + ((kg ^ (r & 7)) << 3)) * 2);
        }
        uint32_t b[2][4];
#pragma unroll
        for (int nt2 = 0; nt2 < 2; nt2++) {
            int n = wn + nt2 * 16 + (lane & 7) + ((lane >> 4) << 3);
            int kg = kk * 2 + ((lane >> 3) & 1);
            ldm4(b[nt2][0], b[nt2][1], b[nt2][2], b[nt2][3],
                 sB + (uint32_t)(n * 128 + ((kg ^ (n & 7)) << 3)) * 2);
        }
#pragma unroll
        for (int mt = 0; mt < 2; mt++)
#pragma unroll
            for (int nt = 0; nt < 4; nt++) {
                int nt2 = nt >> 1, sub = nt & 1;
                mma16816(acc[mt][nt], a[mt], b[nt2][sub * 2], b[nt2][sub * 2 + 1]);
            }
    }

    // epilogue: fp32 + fp16 copies
#pragma unroll
    for (int mt = 0; mt < 2; mt++) {
        int r0 = bm + wm + mt * 16 + (lane >> 2);
#pragma unroll
        for (int half = 0; half < 2; half++) {
            int r = r0 + half * 8;
            if (r < N_) {
#pragma unroll
                for (int nt = 0; nt < 4; nt++) {
                    int cc = bn + wn + nt * 8 + (lane & 3) * 2;
                    float2 v = make_float2(acc[mt][nt][half * 2],
                                           acc[mt][nt][half * 2 + 1]);
                    *(float2*)(C + (size_t)r * CO + cc) = v;
                    *(__half2*)(Ch + (size_t)r * CO + cc) = __floats2half2_rn(v.x, v.y);
                }
            }
        }
    }
}

// ------- GCN aggregate (gather, fp16 neighbors) + bias + BN + ReLU ----------
__global__ void __launch_bounds__(256) k_gcn_gather(
    const float* __restrict__ h, const __half* __restrict__ hh,
    float* __restrict__ out, __half* __restrict__ outh,
    const float* __restrict__ bias, const float* __restrict__ gamma,
    const float* __restrict__ beta, const float* __restrict__ mean,
    const float* __restrict__ var) {
    int n = (blockIdx.x * 256 + threadIdx.x) >> 5;
    if (n >= N_) return;
    int lane = threadIdx.x & 31, c = lane * 4;
    float din = g_dinv[n];
    float ws = din * din;
    float4 acc = *(const float4*)(h + (size_t)n * 128 + c);  // fp32 self
    acc.x *= ws; acc.y *= ws; acc.z *= ws; acc.w *= ws;
    int beg = g_rowstart[n], end = g_rowstart[n + 1];
    int j = beg;
    for (; j + 1 < end; j += 2) {
        int s0 = g_esrc[j], s1 = g_esrc[j + 1];
        float w0 = g_dinv[s0] * din, w1 = g_dinv[s1] * din;
        float4 v0 = ld_h4(hh + (size_t)s0 * 128 + c);
        float4 v1 = ld_h4(hh + (size_t)s1 * 128 + c);
        acc.x += w0 * v0.x + w1 * v1.x;
        acc.y += w0 * v0.y + w1 * v1.y;
        acc.z += w0 * v0.z + w1 * v1.z;
        acc.w += w0 * v0.w + w1 * v1.w;
    }
    if (j < end) {
        int s0 = g_esrc[j];
        float w0 = g_dinv[s0] * din;
        float4 v0 = ld_h4(hh + (size_t)s0 * 128 + c);
        acc.x += w0 * v0.x; acc.y += w0 * v0.y;
        acc.z += w0 * v0.z; acc.w += w0 * v0.w;
    }
    float4 o;
    float* ap = &acc.x; float* op = &o.x;
#pragma unroll
    for (int i = 0; i < 4; i++) {
        int ci = c + i;
        float v = ap[i] + bias[ci];
        v = (v - mean[ci]) * rsqrtf(var[ci] + 1e-5f) * gamma[ci] + beta[ci];
        op[i] = fmaxf(v, 0.f);
    }
    *(float4*)(out + (size_t)n * 128 + c) = o;
    *(uint2*)(outh + (size_t)n * 128 + c) = f4_to_h4(o);
}

// ------- GAT aggregate (fp16 neighbors), C=128, + head-mean + bias + ReLU ---
__global__ void __launch_bounds__(256) k_gat_gather128(
    const float* __restrict__ hg, const __half* __restrict__ hgh,
    float* __restrict__ out, __half* __restrict__ outh,
    const float* __restrict__ bias) {
    int n = (blockIdx.x * 256 + threadIdx.x) >> 5;
    if (n >= N_) return;
    int lane = threadIdx.x & 31, c = lane * 4;
    float ald0 = g_ald[n * 2], ald1 = g_ald[n * 2 + 1];
    float e0s = lrelu(g_als[n * 2] + ald0);
    float e1s = lrelu(g_als[n * 2 + 1] + ald1);
    int beg = g_rowstart[n], end = g_rowstart[n + 1];
    float m0 = e0s, m1 = e1s;
    for (int j = beg; j < end; j++) {
        int s = g_esrc[j];
        m0 = fmaxf(m0, lrelu(g_als[s * 2] + ald0));
        m1 = fmaxf(m1, lrelu(g_als[s * 2 + 1] + ald1));
    }
    float den0 = __expf(e0s - m0), den1 = __expf(e1s - m1);
    const float* hn = hg + (size_t)n * 256;  // fp32 self
    float4 a0 = *(const float4*)(hn + c);
    float4 a1 = *(const float4*)(hn + 128 + c);
    float4 acc0 = make_float4(den0 * a0.x, den0 * a0.y, den0 * a0.z, den0 * a0.w);
    float4 acc1 = make_float4(den1 * a1.x, den1 * a1.y, den1 * a1.z, den1 * a1.w);
    for (int j = beg; j < end; j++) {
        int s = g_esrc[j];
        float w0 = __expf(lrelu(g_als[s * 2] + ald0) - m0);
        float w1 = __expf(lrelu(g_als[s * 2 + 1] + ald1) - m1);
        den0 += w0; den1 += w1;
        const __half* hs = hgh + (size_t)s * 256;
        float4 v0 = ld_h4(hs + c);
        float4 v1 = ld_h4(hs + 128 + c);
        acc0.x += w0 * v0.x; acc0.y += w0 * v0.y;
        acc0.z += w0 * v0.z; acc0.w += w0 * v0.w;
        acc1.x += w1 * v1.x; acc1.y += w1 * v1.y;
        acc1.z += w1 * v1.z; acc1.w += w1 * v1.w;
    }
    float r0 = 0.5f / den0, r1 = 0.5f / den1;
    float4 o;
    o.x = fmaxf(acc0.x * r0 + acc1.x * r1 + bias[c + 0], 0.f);
    o.y = fmaxf(acc0.y * r0 + acc1.y * r1 + bias[c + 1], 0.f);
    o.z = fmaxf(acc0.z * r0 + acc1.z * r1 + bias[c + 2], 0.f);
    o.w = fmaxf(acc0.w * r0 + acc1.w * r1 + bias[c + 3], 0.f);
    *(float4*)(out + (size_t)n * 128 + c) = o;
    *(uint2*)(outh + (size_t)n * 128 + c) = f4_to_h4(o);
}

// ------- GAT aggregate (fp16), C=64, + head-mean + bias + log_softmax -------
__global__ void __launch_bounds__(256) k_gat_gather64(
    const float* __restrict__ hg, const __half* __restrict__ hgh,
    float* __restrict__ out, const float* __restrict__ bias) {
    int n = (blockIdx.x * 256 + threadIdx.x) >> 5;
    if (n >= N_) return;
    int lane = threadIdx.x & 31;
    int h = lane >> 4, cl = lane & 15, c = cl * 4;
    float ald = g_ald[n * 2 + h];
    float es = lrelu(g_als[n * 2 + h] + ald);
    int beg = g_rowstart[n], end = g_rowstart[n + 1];
    float m = es;
    for (int j = beg; j < end; j++) {
        int s = g_esrc[j];
        m = fmaxf(m, lrelu(g_als[s * 2 + h] + ald));
    }
    float den = __expf(es - m);
    const float* hn = hg + (size_t)n * 128 + h * 64;  // fp32 self
    float4 a = *(const float4*)(hn + c);
    float4 acc = make_float4(den * a.x, den * a.y, den * a.z, den * a.w);
    for (int j = beg; j < end; j++) {
        int s = g_esrc[j];
        float w = __expf(lrelu(g_als[s * 2 + h] + ald) - m);
        den += w;
        float4 v = ld_h4(hgh + (size_t)s * 128 + h * 64 + c);
        acc.x += w * v.x; acc.y += w * v.y;
        acc.z += w * v.z; acc.w += w * v.w;
    }
    float inv = 1.f / den;
    float4 v = make_float4(acc.x * inv, acc.y * inv, acc.z * inv, acc.w * inv);
    float4 o;
    o.x = 0.5f * (v.x + __shfl_xor_sync(0xffffffffu, v.x, 16)) + bias[c + 0];
    o.y = 0.5f * (v.y + __shfl_xor_sync(0xffffffffu, v.y, 16)) + bias[c + 1];
    o.z = 0.5f * (v.z + __shfl_xor_sync(0xffffffffu, v.z, 16)) + bias[c + 2];
    o.w = 0.5f * (v.w + __shfl_xor_sync(0xffffffffu, v.w, 16)) + bias[c + 3];
    float lm = fmaxf(fmaxf(o.x, o.y), fmaxf(o.z, o.w));
#pragma unroll
    for (int off = 8; off; off >>= 1) lm = fmaxf(lm, __shfl_xor_sync(0xffffffffu, lm, off));
    float sum = __expf(o.x - lm) + __expf(o.y - lm) + __expf(o.z - lm) + __expf(o.w - lm);
#pragma unroll
    for (int off = 8; off; off >>= 1) sum += __shfl_xor_sync(0xffffffffu, sum, off);
    float l = lm + logf(sum);
    if (lane < 16) {
        float4 r = make_float4(o.x - l, o.y - l, o.z - l, o.w - l);
        *(float4*)(out + (size_t)n * 64 + c) = r;
    }
}

// ---------------- launch -----------------------------------------------------
extern "C" void kernel_launch(void* const* d_in, const int* in_sizes, int n_in,
                              void* d_out, int out_size) {
    const float* x   = (const float*)d_in[0];
    const void*  ei  = d_in[1];
    const float* Wg1 = (const float*)d_in[2];
    const float* bg1 = (const float*)d_in[3];
    const float* g1g = (const float*)d_in[4];
    const float* g1b = (const float*)d_in[5];
    const float* g1m = (const float*)d_in[6];
    const float* g1v = (const float*)d_in[7];
    const float* Wa1 = (const float*)d_in[8];
    const float* as1 = (const float*)d_in[9];
    const float* ad1 = (const float*)d_in[10];
    const float* ba1 = (const float*)d_in[11];
    const float* Wg2 = (const float*)d_in[12];
    const float* bg2 = (const float*)d_in[13];
    const float* g2g = (const float*)d_in[14];
    const float* g2b = (const float*)d_in[15];
    const float* g2m = (const float*)d_in[16];
    const float* g2v = (const float*)d_in[17];
    const float* Wa2 = (const float*)d_in[18];
    const float* as2 = (const float*)d_in[19];
    const float* ad2 = (const float*)d_in[20];
    const float* ba2 = (const float*)d_in[21];
    float* out = (float*)d_out;

    float *bufA, *bufC;
    __half *bufAh, *bufCh, *wt, *xh;
    cudaGetSymbolAddress((void**)&bufA, g_bufA);
    cudaGetSymbolAddress((void**)&bufAh, g_bufAh);
    cudaGetSymbolAddress((void**)&bufC, g_bufC);
    cudaGetSymbolAddress((void**)&bufCh, g_bufCh);
    cudaGetSymbolAddress((void**)&wt, g_wt);
    cudaGetSymbolAddress((void**)&xh, g_xh);

    const int TB = 256;
    const int nb = (N_ + TB - 1) / TB;
    const int eb = (E_ + TB - 1) / TB;
    const int nw = (N_ * 32 + TB - 1) / TB;   // warp per node
    const int GX = (N_ + 127) / 128;          // 391 GEMM row tiles

    // ---- preprocessing: dtype detect, deg, CSR (parallel scan)
    k_prep<<<nb, TB>>>(ei);
    k_convert<<<eb, TB>>>(ei);
    k_scan1<<<SB, TB>>>();
    k_scan2<<<1, TB>>>();
    k_scan3<<<SB, TB>>>();
    k_csr<<<eb, TB>>>();
    k_x2h<<<(N_ * 32 + TB - 1) / TB, TB>>>(x, xh);

    // ---- GCN1 (+ bias + BN1 + ReLU fused into gather)
    k_wcvt<<<(128 * 128) / TB, TB>>>(Wg1, wt, 128);
    k_gemm_h<<<dim3(GX, 2), TB>>>(xh, wt, bufA, bufAh, 128);
    k_gcn_gather<<<nw, TB>>>(bufA, bufAh, bufC, bufCh, bg1, g1g, g1b, g1m, g1v);

    // ---- GAT1 (+ head-mean + bias + ReLU fused)
    k_wcvt<<<(256 * 128) / TB, TB>>>(Wa1, wt, 256);
    k_gemm_h<<<dim3(GX, 4), TB>>>(bufCh, wt, bufA, bufAh, 256);
    k_va<<<4, 128>>>(Wa1, as1, ad1, 256, 128);
    k_alv<<<nw, TB>>>(bufCh);
    k_gat_gather128<<<nw, TB>>>(bufA, bufAh, bufC, bufCh, ba1);

    // ---- GCN2 (+ bias + BN2 + ReLU fused)
    k_wcvt<<<(128 * 128) / TB, TB>>>(Wg2, wt, 128);
    k_gemm_h<<<dim3(GX, 2), TB>>>(bufCh, wt, bufA, bufAh, 128);
    k_gcn_gather<<<nw, TB>>>(bufA, bufAh, bufC, bufCh, bg2, g2g, g2b, g2m, g2v);

    // ---- GAT2 (+ head-mean + bias + log_softmax fused)
    k_wcvt<<<(128 * 128) / TB, TB>>>(Wa2, wt, 128);
    k_gemm_h<<<dim3(GX, 2), TB>>>(bufCh, wt, bufA, bufAh, 128);
    k_va<<<4, 128>>>(Wa2, as2, ad2, 128, 64);
    k_alv<<<nw, TB>>>(bufCh);
    k_gat_gather64<<<nw, TB>>>(bufA, bufAh, out, ba2);
}

// round 10
// speedup vs baseline: 2.4861x; 1.0837x over previous
#include <cuda_runtime.h>
#include <cuda_fp16.h>
#include <math.h>
#include <stddef.h>
#include <stdint.h>

#define N_ 50000
#define E_ 600000
#define SB 200     // scan blocks
#define NPB 250    // nodes per scan block (200*250 = 50000)

// ---------------- device scratch (no allocations allowed) -------------------
__device__ int      g_src[E_];
__device__ int      g_dst[E_];
__device__ int      g_esrc[E_];         // CSR: src ids grouped by dst
__device__ int      g_rowstart[N_ + 1]; // CSR offsets
__device__ int      g_deg[N_];
__device__ int      g_fill[N_];
__device__ int      g_bsum[SB];
__device__ int      g_bpre[SB];
__device__ float    g_dinv[N_];
__device__ int      g_flag;             // 1 = edge_index is int64, 0 = int32
__device__ float    g_als[N_ * 2];
__device__ float    g_ald[N_ * 2];
__device__ float    g_va[4 * 128];      // folded attention projections W@a
__device__ __half   g_wt[256 * 128];    // transposed fp16 weights [CO][128]
__device__ __half   g_xh[N_ * 128];     // fp16 copy of input x
__device__ __half   g_bufAh[N_ * 256];  // GEMM outputs fp16
__device__ __half   g_bufCh[N_ * 128];  // activations fp16 (GEMM feed)
__device__ float    g_bufC[N_ * 128];   // activations fp32 (unused carry; kept small use)

// ---------------- helpers ---------------------------------------------------
__device__ __forceinline__ float lrelu(float e) { return e > 0.f ? e : 0.2f * e; }

__device__ __forceinline__ float wred_sum(float v) {
#pragma unroll
    for (int o = 16; o; o >>= 1) v += __shfl_xor_sync(0xffffffffu, v, o);
    return v;
}

__device__ __forceinline__ float4 ld_h4(const __half* p) {
    uint2 u = *(const uint2*)p;
    __half2 h0 = *(__half2*)&u.x, h1 = *(__half2*)&u.y;
    float2 f0 = __half22float2(h0), f1 = __half22float2(h1);
    return make_float4(f0.x, f0.y, f1.x, f1.y);
}
__device__ __forceinline__ uint2 f4_to_h4(float4 v) {
    __half2 h0 = __floats2half2_rn(v.x, v.y);
    __half2 h1 = __floats2half2_rn(v.z, v.w);
    uint2 u;
    u.x = *(unsigned*)&h0; u.y = *(unsigned*)&h1;
    return u;
}
__device__ __forceinline__ uint32_t smem_u32(const void* p) {
    return (uint32_t)__cvta_generic_to_shared(p);
}
__device__ __forceinline__ void ldm4(uint32_t& r0, uint32_t& r1, uint32_t& r2,
                                     uint32_t& r3, uint32_t addr) {
    asm volatile("ldmatrix.sync.aligned.m8n8.x4.shared.b16 {%0,%1,%2,%3}, [%4];"
                 : "=r"(r0), "=r"(r1), "=r"(r2), "=r"(r3) : "r"(addr));
}
__device__ __forceinline__ void mma16816(float* d, const uint32_t* a,
                                         uint32_t b0, uint32_t b1) {
    asm volatile(
        "mma.sync.aligned.m16n8k16.row.col.f32.f16.f16.f32 "
        "{%0,%1,%2,%3}, {%4,%5,%6,%7}, {%8,%9}, {%0,%1,%2,%3};"
        : "+f"(d[0]), "+f"(d[1]), "+f"(d[2]), "+f"(d[3])
        : "r"(a[0]), "r"(a[1]), "r"(a[2]), "r"(a[3]), "r"(b0), "r"(b1));
}

// ---------------- preprocessing ---------------------------------------------
__global__ void k_prep(const void* eidx) {
    int i = blockIdx.x * 256 + threadIdx.x;
    if (i < N_) g_deg[i] = 0;
    if (i == 0) {
        const long long* p = (const long long*)eidx;
        int ok = 1;
        for (int j = 0; j < 128; j++) {
            long long v = p[j];
            if (v < 0 || v >= N_) { ok = 0; break; }
        }
        g_flag = ok;
    }
}

__global__ void k_convert(const void* eidx) {
    int i = blockIdx.x * 256 + threadIdx.x;
    if (i >= E_) return;
    int s, d;
    if (g_flag) {
        const long long* p = (const long long*)eidx;
        s = (int)p[i]; d = (int)p[E_ + i];
    } else {
        const int* p = (const int*)eidx;
        s = p[i]; d = p[E_ + i];
    }
    g_src[i] = s; g_dst[i] = d;
    atomicAdd(&g_deg[d], 1);
}

__global__ void __launch_bounds__(256) k_scan1() {
    __shared__ int sh[256];
    int t = threadIdx.x, b = blockIdx.x;
    int i = b * NPB + t;
    sh[t] = (t < NPB) ? g_deg[i] : 0;
    __syncthreads();
    for (int off = 128; off; off >>= 1) {
        if (t < off) sh[t] += sh[t + off];
        __syncthreads();
    }
    if (t == 0) g_bsum[b] = sh[0];
}

__global__ void __launch_bounds__(256) k_scan2() {
    __shared__ int sh[256];
    int t = threadIdx.x;
    int v = (t < SB) ? g_bsum[t] : 0;
    sh[t] = v;
    __syncthreads();
    for (int off = 1; off < 256; off <<= 1) {
        int u = (t >= off) ? sh[t - off] : 0;
        __syncthreads();
        sh[t] += u;
        __syncthreads();
    }
    if (t < SB) g_bpre[t] = sh[t] - v;  // exclusive
}

__global__ void __launch_bounds__(256) k_scan3() {
    __shared__ int sh[256];
    int t = threadIdx.x, b = blockIdx.x;
    int i = b * NPB + t;
    int d = (t < NPB) ? g_deg[i] : 0;
    sh[t] = d;
    __syncthreads();
    for (int off = 1; off < 256; off <<= 1) {
        int u = (t >= off) ? sh[t - off] : 0;
        __syncthreads();
        sh[t] += u;
        __syncthreads();
    }
    if (t < NPB) {
        g_rowstart[i] = g_bpre[b] + sh[t] - d;
        g_dinv[i] = rsqrtf((float)(d + 1));  // +1 self loop
        g_fill[i] = 0;
    }
    if (b == SB - 1 && t == 0) g_rowstart[N_] = E_;
}

__global__ void k_csr() {
    int i = blockIdx.x * 256 + threadIdx.x;
    if (i >= E_) return;
    int d = g_dst[i];
    int pos = g_rowstart[d] + atomicAdd(&g_fill[d], 1);
    g_esrc[pos] = g_src[i];
}

// ---------------- conversions -----------------------------------------------
__global__ void k_x2h(const float* __restrict__ x, __half* __restrict__ xh) {
    int i = blockIdx.x * 256 + threadIdx.x;
    if (i < N_ * 32) {
        float4 v = *(const float4*)(x + (size_t)i * 4);
        *(uint2*)(xh + (size_t)i * 4) = f4_to_h4(v);
    }
}

// W [128, CO] fp32 -> Wt [CO][128] fp16 (transposed, K-contiguous)
__global__ void k_wcvt(const float* __restrict__ W, __half* __restrict__ Wt, int CO) {
    int idx = blockIdx.x * 256 + threadIdx.x;
    if (idx >= CO * 128) return;
    int n = idx >> 7, k = idx & 127;
    Wt[idx] = __float2half(W[(size_t)k * CO + n]);
}

// va[j][k] = sum_c W[k][h*C + c] * a[h][c]; j: 0,1=src h0,h1; 2,3=dst h0,h1
__global__ void k_va(const float* __restrict__ W, const float* __restrict__ asrc,
                     const float* __restrict__ adst, int CO, int C) {
    int j = blockIdx.x, k = threadIdx.x;
    const float* a = (j < 2) ? asrc : adst;
    int h = j & 1;
    float s = 0.f;
    for (int c = 0; c < C; c++) s += W[(size_t)k * CO + h * C + c] * a[h * C + c];
    g_va[j * 128 + k] = s;
}

// attention logits from GEMM *input* (fp16): al = x @ va
__global__ void __launch_bounds__(256) k_alv(const __half* __restrict__ Ah) {
    __shared__ float vs[4][128];
    int tid = threadIdx.x;
    for (int i = tid; i < 512; i += 256) vs[i >> 7][i & 127] = g_va[i];
    __syncthreads();
    int n = (blockIdx.x * 256 + tid) >> 5;
    if (n >= N_) return;
    int lane = tid & 31, c = lane * 4;
    float4 v = ld_h4(Ah + (size_t)n * 128 + c);
    float r[4];
#pragma unroll
    for (int j = 0; j < 4; j++) {
        float s = v.x * vs[j][c] + v.y * vs[j][c + 1] +
                  v.z * vs[j][c + 2] + v.w * vs[j][c + 3];
        r[j] = wred_sum(s);
    }
    if (lane == 0) {
        g_als[n * 2 + 0] = r[0]; g_als[n * 2 + 1] = r[1];
        g_ald[n * 2 + 0] = r[2]; g_ald[n * 2 + 1] = r[3];
    }
}

// ---- HMMA GEMM: Ch[N,CO] = A[N,128](fp16) @ Wt[CO,128](fp16)^T (fp16 out) --
__global__ void __launch_bounds__(256) k_gemm_h(const __half* __restrict__ A,
                                                const __half* __restrict__ Wt,
                                                __half* __restrict__ Ch, int CO) {
    __shared__ __half As[128 * 128];  // row r: granule g stored at (g ^ (r&7))
    __shared__ __half Bs[64 * 128];
    const int bm = blockIdx.x * 128, bn = blockIdx.y * 64;
    const int tid = threadIdx.x;
    const int warp = tid >> 5, lane = tid & 31;

    {
        int r = tid >> 1, hh = tid & 1;
        int gr = bm + r;
        const uint4* src = (const uint4*)(A + (size_t)gr * 128 + hh * 64);
        uint4 z = make_uint4(0, 0, 0, 0);
#pragma unroll
        for (int g = 0; g < 8; g++) {
            int gg = hh * 8 + g;
            uint4 v = (gr < N_) ? src[g] : z;
            *(uint4*)&As[r * 128 + ((gg ^ (r & 7)) << 3)] = v;
        }
    }
    {
        int n = tid >> 2, q = tid & 3;
        const uint4* src = (const uint4*)(Wt + (size_t)(bn + n) * 128 + q * 32);
#pragma unroll
        for (int g = 0; g < 4; g++) {
            int gg = q * 4 + g;
            uint4 v = src[g];
            *(uint4*)&Bs[n * 128 + ((gg ^ (n & 7)) << 3)] = v;
        }
    }
    __syncthreads();

    const uint32_t sA = smem_u32(As), sB = smem_u32(Bs);
    const int wm = (warp & 3) * 32, wn = (warp >> 2) * 32;
    float acc[2][4][4];
#pragma unroll
    for (int mt = 0; mt < 2; mt++)
#pragma unroll
        for (int nt = 0; nt < 4; nt++)
#pragma unroll
            for (int i = 0; i < 4; i++) acc[mt][nt][i] = 0.f;

#pragma unroll
    for (int kk = 0; kk < 8; kk++) {
        uint32_t a[2][4];
#pragma unroll
        for (int mt = 0; mt < 2; mt++) {
            int r = wm + mt * 16 + (lane & 15);
            int kg = kk * 2 + (lane >> 4);
            ldm4(a[mt][0], a[mt][1], a[mt][2], a[mt][3],
                 sA + (uint32_t)(r * 128 + ((kg ^ (r & 7)) << 3)) * 2);
        }
        uint32_t b[2][4];
#pragma unroll
        for (int nt2 = 0; nt2 < 2; nt2++) {
            int n = wn + nt2 * 16 + (lane & 7) + ((lane >> 4) << 3);
            int kg = kk * 2 + ((lane >> 3) & 1);
            ldm4(b[nt2][0], b[nt2][1], b[nt2][2], b[nt2][3],
                 sB + (uint32_t)(n * 128 + ((kg ^ (n & 7)) << 3)) * 2);
        }
#pragma unroll
        for (int mt = 0; mt < 2; mt++)
#pragma unroll
            for (int nt = 0; nt < 4; nt++) {
                int nt2 = nt >> 1, sub = nt & 1;
                mma16816(acc[mt][nt], a[mt], b[nt2][sub * 2], b[nt2][sub * 2 + 1]);
            }
    }

#pragma unroll
    for (int mt = 0; mt < 2; mt++) {
        int r0 = bm + wm + mt * 16 + (lane >> 2);
#pragma unroll
        for (int half = 0; half < 2; half++) {
            int r = r0 + half * 8;
            if (r < N_) {
#pragma unroll
                for (int nt = 0; nt < 4; nt++) {
                    int cc = bn + wn + nt * 8 + (lane & 3) * 2;
                    *(__half2*)(Ch + (size_t)r * CO + cc) =
                        __floats2half2_rn(acc[mt][nt][half * 2],
                                          acc[mt][nt][half * 2 + 1]);
                }
            }
        }
    }
}

// ------- GCN aggregate (chunk-parallel indices) + bias + BN + ReLU ----------
__global__ void __launch_bounds__(256) k_gcn_gather(
    const __half* __restrict__ hh, __half* __restrict__ outh,
    const float* __restrict__ bias, const float* __restrict__ gamma,
    const float* __restrict__ beta, const float* __restrict__ mean,
    const float* __restrict__ var) {
    int n = (blockIdx.x * 256 + threadIdx.x) >> 5;
    if (n >= N_) return;
    int lane = threadIdx.x & 31, c = lane * 4;
    float din = g_dinv[n];
    float ws = din * din;
    float4 acc = ld_h4(hh + (size_t)n * 128 + c);  // self (fp16)
    acc.x *= ws; acc.y *= ws; acc.z *= ws; acc.w *= ws;
    int beg = g_rowstart[n];
    int deg = g_rowstart[n + 1] - beg;
    for (int base = 0; base < deg; base += 32) {
        int cnt = min(32, deg - base);
        int s = 0; float w = 0.f;
        if (lane < cnt) { s = g_esrc[beg + base + lane]; w = g_dinv[s] * din; }
        for (int j = 0; j < cnt; j++) {
            int sj = __shfl_sync(0xffffffffu, s, j);
            float wj = __shfl_sync(0xffffffffu, w, j);
            float4 v = ld_h4(hh + (size_t)sj * 128 + c);
            acc.x += wj * v.x; acc.y += wj * v.y;
            acc.z += wj * v.z; acc.w += wj * v.w;
        }
    }
    float4 o;
    float* ap = &acc.x; float* op = &o.x;
#pragma unroll
    for (int i = 0; i < 4; i++) {
        int ci = c + i;
        float v = ap[i] + bias[ci];
        v = (v - mean[ci]) * rsqrtf(var[ci] + 1e-5f) * gamma[ci] + beta[ci];
        op[i] = fmaxf(v, 0.f);
    }
    *(uint2*)(outh + (size_t)n * 128 + c) = f4_to_h4(o);
}

// ------- GAT aggregate (chunk-parallel), C=128, + head-mean + bias + ReLU ---
__global__ void __launch_bounds__(256) k_gat_gather128(
    const __half* __restrict__ hgh, __half* __restrict__ outh,
    const float* __restrict__ bias) {
    int n = (blockIdx.x * 256 + threadIdx.x) >> 5;
    if (n >= N_) return;
    int lane = threadIdx.x & 31, c = lane * 4;
    float ald0 = g_ald[n * 2], ald1 = g_ald[n * 2 + 1];
    float e0s = lrelu(g_als[n * 2] + ald0);
    float e1s = lrelu(g_als[n * 2 + 1] + ald1);
    int beg = g_rowstart[n];
    int deg = g_rowstart[n + 1] - beg;

    // pass 1: chunk-parallel max
    float m0 = e0s, m1 = e1s;
    for (int base = 0; base < deg; base += 32) {
        int cnt = min(32, deg - base);
        float e0 = -1e30f, e1 = -1e30f;
        if (lane < cnt) {
            int s = g_esrc[beg + base + lane];
            float2 al = *(const float2*)&g_als[2 * s];
            e0 = lrelu(al.x + ald0); e1 = lrelu(al.y + ald1);
        }
#pragma unroll
        for (int off = 16; off; off >>= 1) {
            e0 = fmaxf(e0, __shfl_xor_sync(0xffffffffu, e0, off));
            e1 = fmaxf(e1, __shfl_xor_sync(0xffffffffu, e1, off));
        }
        m0 = fmaxf(m0, e0); m1 = fmaxf(m1, e1);
    }

    float den0 = __expf(e0s - m0), den1 = __expf(e1s - m1);
    const __half* hn = hgh + (size_t)n * 256;  // self (fp16)
    float4 a0 = ld_h4(hn + c);
    float4 a1 = ld_h4(hn + 128 + c);
    float4 acc0 = make_float4(den0 * a0.x, den0 * a0.y, den0 * a0.z, den0 * a0.w);
    float4 acc1 = make_float4(den1 * a1.x, den1 * a1.y, den1 * a1.z, den1 * a1.w);

    // pass 2: chunk-parallel weights, broadcast accumulate
    for (int base = 0; base < deg; base += 32) {
        int cnt = min(32, deg - base);
        int s = 0; float w0 = 0.f, w1 = 0.f;
        if (lane < cnt) {
            s = g_esrc[beg + base + lane];
            float2 al = *(const float2*)&g_als[2 * s];
            w0 = __expf(lrelu(al.x + ald0) - m0);
            w1 = __expf(lrelu(al.y + ald1) - m1);
        }
        den0 += wred_sum(w0); den1 += wred_sum(w1);
        for (int j = 0; j < cnt; j++) {
            int sj = __shfl_sync(0xffffffffu, s, j);
            float w0j = __shfl_sync(0xffffffffu, w0, j);
            float w1j = __shfl_sync(0xffffffffu, w1, j);
            const __half* hs = hgh + (size_t)sj * 256;
            float4 v0 = ld_h4(hs + c);
            float4 v1 = ld_h4(hs + 128 + c);
            acc0.x += w0j * v0.x; acc0.y += w0j * v0.y;
            acc0.z += w0j * v0.z; acc0.w += w0j * v0.w;
            acc1.x += w1j * v1.x; acc1.y += w1j * v1.y;
            acc1.z += w1j * v1.z; acc1.w += w1j * v1.w;
        }
    }
    float r0 = 0.5f / den0, r1 = 0.5f / den1;
    float4 o;
    o.x = fmaxf(acc0.x * r0 + acc1.x * r1 + bias[c + 0], 0.f);
    o.y = fmaxf(acc0.y * r0 + acc1.y * r1 + bias[c + 1], 0.f);
    o.z = fmaxf(acc0.z * r0 + acc1.z * r1 + bias[c + 2], 0.f);
    o.w = fmaxf(acc0.w * r0 + acc1.w * r1 + bias[c + 3], 0.f);
    *(uint2*)(outh + (size_t)n * 128 + c) = f4_to_h4(o);
}

// ------- GAT aggregate, C=64 (half-warp per head) + bias + log_softmax ------
__global__ void __launch_bounds__(256) k_gat_gather64(
    const __half* __restrict__ hgh,
    float* __restrict__ out, const float* __restrict__ bias) {
    int n = (blockIdx.x * 256 + threadIdx.x) >> 5;
    if (n >= N_) return;
    int lane = threadIdx.x & 31;
    int h = lane >> 4, cl = lane & 15, c = cl * 4;
    float ald = g_ald[n * 2 + h];
    float es = lrelu(g_als[n * 2 + h] + ald);
    int beg = g_rowstart[n];
    int deg = g_rowstart[n + 1] - beg;

    // pass 1: chunk-parallel max (16-lane chunks per head)
    float m = es;
    for (int base = 0; base < deg; base += 16) {
        int cnt = min(16, deg - base);
        float e = -1e30f;
        if (cl < cnt) {
            int s = g_esrc[beg + base + cl];
            e = lrelu(g_als[2 * s + h] + ald);
        }
#pragma unroll
        for (int off = 8; off; off >>= 1)
            e = fmaxf(e, __shfl_xor_sync(0xffffffffu, e, off));
        m = fmaxf(m, e);
    }

    float den = __expf(es - m);
    const __half* hn = hgh + (size_t)n * 128 + h * 64;  // self (fp16)
    float4 a = ld_h4(hn + c);
    float4 acc = make_float4(den * a.x, den * a.y, den * a.z, den * a.w);

    // pass 2
    for (int base = 0; base < deg; base += 16) {
        int cnt = min(16, deg - base);
        int s = 0; float w = 0.f;
        if (cl < cnt) {
            s = g_esrc[beg + base + cl];
            w = __expf(lrelu(g_als[2 * s + h] + ald) - m);
        }
        float t = w;
#pragma unroll
        for (int off = 8; off; off >>= 1) t += __shfl_xor_sync(0xffffffffu, t, off);
        den += t;
        for (int j = 0; j < cnt; j++) {
            int sj = __shfl_sync(0xffffffffu, s, (h << 4) | j);
            float wj = __shfl_sync(0xffffffffu, w, (h << 4) | j);
            float4 v = ld_h4(hgh + (size_t)sj * 128 + h * 64 + c);
            acc.x += wj * v.x; acc.y += wj * v.y;
            acc.z += wj * v.z; acc.w += wj * v.w;
        }
    }
    float inv = 1.f / den;
    float4 v = make_float4(acc.x * inv, acc.y * inv, acc.z * inv, acc.w * inv);
    float4 o;
    o.x = 0.5f * (v.x + __shfl_xor_sync(0xffffffffu, v.x, 16)) + bias[c + 0];
    o.y = 0.5f * (v.y + __shfl_xor_sync(0xffffffffu, v.y, 16)) + bias[c + 1];
    o.z = 0.5f * (v.z + __shfl_xor_sync(0xffffffffu, v.z, 16)) + bias[c + 2];
    o.w = 0.5f * (v.w + __shfl_xor_sync(0xffffffffu, v.w, 16)) + bias[c + 3];
    float lm = fmaxf(fmaxf(o.x, o.y), fmaxf(o.z, o.w));
#pragma unroll
    for (int off = 8; off; off >>= 1) lm = fmaxf(lm, __shfl_xor_sync(0xffffffffu, lm, off));
    float sum = __expf(o.x - lm) + __expf(o.y - lm) + __expf(o.z - lm) + __expf(o.w - lm);
#pragma unroll
    for (int off = 8; off; off >>= 1) sum += __shfl_xor_sync(0xffffffffu, sum, off);
    float l = lm + logf(sum);
    if (lane < 16) {
        float4 r = make_float4(o.x - l, o.y - l, o.z - l, o.w - l);
        *(float4*)(out + (size_t)n * 64 + c) = r;
    }
}

// ---------------- launch -----------------------------------------------------
extern "C" void kernel_launch(void* const* d_in, const int* in_sizes, int n_in,
                              void* d_out, int out_size) {
    const float* x   = (const float*)d_in[0];
    const void*  ei  = d_in[1];
    const float* Wg1 = (const float*)d_in[2];
    const float* bg1 = (const float*)d_in[3];
    const float* g1g = (const float*)d_in[4];
    const float* g1b = (const float*)d_in[5];
    const float* g1m = (const float*)d_in[6];
    const float* g1v = (const float*)d_in[7];
    const float* Wa1 = (const float*)d_in[8];
    const float* as1 = (const float*)d_in[9];
    const float* ad1 = (const float*)d_in[10];
    const float* ba1 = (const float*)d_in[11];
    const float* Wg2 = (const float*)d_in[12];
    const float* bg2 = (const float*)d_in[13];
    const float* g2g = (const float*)d_in[14];
    const float* g2b = (const float*)d_in[15];
    const float* g2m = (const float*)d_in[16];
    const float* g2v = (const float*)d_in[17];
    const float* Wa2 = (const float*)d_in[18];
    const float* as2 = (const float*)d_in[19];
    const float* ad2 = (const float*)d_in[20];
    const float* ba2 = (const float*)d_in[21];
    float* out = (float*)d_out;

    __half *bufAh, *bufCh, *wt, *xh;
    cudaGetSymbolAddress((void**)&bufAh, g_bufAh);
    cudaGetSymbolAddress((void**)&bufCh, g_bufCh);
    cudaGetSymbolAddress((void**)&wt, g_wt);
    cudaGetSymbolAddress((void**)&xh, g_xh);

    const int TB = 256;
    const int nb = (N_ + TB - 1) / TB;
    const int eb = (E_ + TB - 1) / TB;
    const int nw = (N_ * 32 + TB - 1) / TB;   // warp per node
    const int GX = (N_ + 127) / 128;          // 391 GEMM row tiles

    // ---- preprocessing: dtype detect, deg, CSR (parallel scan)
    k_prep<<<nb, TB>>>(ei);
    k_convert<<<eb, TB>>>(ei);
    k_scan1<<<SB, TB>>>();
    k_scan2<<<1, TB>>>();
    k_scan3<<<SB, TB>>>();
    k_csr<<<eb, TB>>>();
    k_x2h<<<(N_ * 32 + TB - 1) / TB, TB>>>(x, xh);

    // ---- GCN1 (+ bias + BN1 + ReLU fused into gather)
    k_wcvt<<<(128 * 128) / TB, TB>>>(Wg1, wt, 128);
    k_gemm_h<<<dim3(GX, 2), TB>>>(xh, wt, bufAh, 128);
    k_gcn_gather<<<nw, TB>>>(bufAh, bufCh, bg1, g1g, g1b, g1m, g1v);

    // ---- GAT1 (+ head-mean + bias + ReLU fused)
    k_wcvt<<<(256 * 128) / TB, TB>>>(Wa1, wt, 256);
    k_gemm_h<<<dim3(GX, 4), TB>>>(bufCh, wt, bufAh, 256);
    k_va<<<4, 128>>>(Wa1, as1, ad1, 256, 128);
    k_alv<<<nw, TB>>>(bufCh);
    k_gat_gather128<<<nw, TB>>>(bufAh, bufCh, ba1);

    // ---- GCN2 (+ bias + BN2 + ReLU fused)
    k_wcvt<<<(128 * 128) / TB, TB>>>(Wg2, wt, 128);
    k_gemm_h<<<dim3(GX, 2), TB>>>(bufCh, wt, bufAh, 128);
    k_gcn_gather<<<nw, TB>>>(bufAh, bufCh, bg2, g2g, g2b, g2m, g2v);

    // ---- GAT2 (+ head-mean + bias + log_softmax fused)
    k_wcvt<<<(128 * 128) / TB, TB>>>(Wa2, wt, 128);
    k_gemm_h<<<dim3(GX, 2), TB>>>(bufCh, wt, bufAh, 128);
    k_va<<<4, 128>>>(Wa2, as2, ad2, 128, 64);
    k_alv<<<nw, TB>>>(bufCh);
    k_gat_gather64<<<nw, TB>>>(bufAh, out, ba2);
}

// round 11
// speedup vs baseline: 2.6988x; 1.0855x over previous
#include <cuda_runtime.h>
#include <cuda_fp16.h>
#include <math.h>
#include <stddef.h>
#include <stdint.h>

#define N_ 50000
#define E_ 600000
#define SB 200     // scan blocks
#define NPB 250    // nodes per scan block (200*250 = 50000)

// ---------------- device scratch (no allocations allowed) -------------------
__device__ int      g_src[E_];
__device__ int      g_dst[E_];
__device__ int      g_esrc[E_];         // CSR: src ids grouped by dst
__device__ int      g_rowstart[N_ + 1]; // CSR offsets
__device__ int      g_deg[N_];
__device__ int      g_fill[N_];
__device__ int      g_bsum[SB];
__device__ int      g_bpre[SB];
__device__ float    g_dinv[N_];
__device__ int      g_flag;             // 1 = edge_index is int64, 0 = int32
__device__ float    g_als[N_ * 2];
__device__ float    g_ald[N_ * 2];
__device__ float    g_va[4 * 128];      // folded attention projections W@a
__device__ __half   g_wt[256 * 128];    // transposed fp16 weights [CO][128]
__device__ __half   g_xh[N_ * 128];     // fp16 copy of input x
__device__ __half   g_bufAh[N_ * 256];  // GEMM outputs fp16
__device__ __half   g_bufCh[N_ * 128];  // activations fp16 (GEMM feed)

// ---------------- helpers ---------------------------------------------------
__device__ __forceinline__ float lrelu(float e) { return e > 0.f ? e : 0.2f * e; }

__device__ __forceinline__ float wred_sum(float v) {
#pragma unroll
    for (int o = 16; o; o >>= 1) v += __shfl_xor_sync(0xffffffffu, v, o);
    return v;
}

__device__ __forceinline__ float4 ld_h4(const __half* p) {
    uint2 u = *(const uint2*)p;
    __half2 h0 = *(__half2*)&u.x, h1 = *(__half2*)&u.y;
    float2 f0 = __half22float2(h0), f1 = __half22float2(h1);
    return make_float4(f0.x, f0.y, f1.x, f1.y);
}
__device__ __forceinline__ uint2 f4_to_h4(float4 v) {
    __half2 h0 = __floats2half2_rn(v.x, v.y);
    __half2 h1 = __floats2half2_rn(v.z, v.w);
    uint2 u;
    u.x = *(unsigned*)&h0; u.y = *(unsigned*)&h1;
    return u;
}
__device__ __forceinline__ uint32_t smem_u32(const void* p) {
    return (uint32_t)__cvta_generic_to_shared(p);
}
__device__ __forceinline__ void ldm4(uint32_t& r0, uint32_t& r1, uint32_t& r2,
                                     uint32_t& r3, uint32_t addr) {
    asm volatile("ldmatrix.sync.aligned.m8n8.x4.shared.b16 {%0,%1,%2,%3}, [%4];"
                 : "=r"(r0), "=r"(r1), "=r"(r2), "=r"(r3) : "r"(addr));
}
__device__ __forceinline__ void mma16816(float* d, const uint32_t* a,
                                         uint32_t b0, uint32_t b1) {
    asm volatile(
        "mma.sync.aligned.m16n8k16.row.col.f32.f16.f16.f32 "
        "{%0,%1,%2,%3}, {%4,%5,%6,%7}, {%8,%9}, {%0,%1,%2,%3};"
        : "+f"(d[0]), "+f"(d[1]), "+f"(d[2]), "+f"(d[3])
        : "r"(a[0]), "r"(a[1]), "r"(a[2]), "r"(a[3]), "r"(b0), "r"(b1));
}

// ---------------- preprocessing ---------------------------------------------
__global__ void k_prep(const void* eidx) {
    int i = blockIdx.x * 256 + threadIdx.x;
    if (i < N_) g_deg[i] = 0;
    if (i == 0) {
        const long long* p = (const long long*)eidx;
        int ok = 1;
        for (int j = 0; j < 128; j++) {
            long long v = p[j];
            if (v < 0 || v >= N_) { ok = 0; break; }
        }
        g_flag = ok;
    }
}

__global__ void k_convert(const void* eidx) {
    int i = blockIdx.x * 256 + threadIdx.x;
    if (i >= E_) return;
    int s, d;
    if (g_flag) {
        const long long* p = (const long long*)eidx;
        s = (int)p[i]; d = (int)p[E_ + i];
    } else {
        const int* p = (const int*)eidx;
        s = p[i]; d = p[E_ + i];
    }
    g_src[i] = s; g_dst[i] = d;
    atomicAdd(&g_deg[d], 1);
}

__global__ void __launch_bounds__(256) k_scan1() {
    __shared__ int sh[256];
    int t = threadIdx.x, b = blockIdx.x;
    int i = b * NPB + t;
    sh[t] = (t < NPB) ? g_deg[i] : 0;
    __syncthreads();
    for (int off = 128; off; off >>= 1) {
        if (t < off) sh[t] += sh[t + off];
        __syncthreads();
    }
    if (t == 0) g_bsum[b] = sh[0];
}

__global__ void __launch_bounds__(256) k_scan2() {
    __shared__ int sh[256];
    int t = threadIdx.x;
    int v = (t < SB) ? g_bsum[t] : 0;
    sh[t] = v;
    __syncthreads();
    for (int off = 1; off < 256; off <<= 1) {
        int u = (t >= off) ? sh[t - off] : 0;
        __syncthreads();
        sh[t] += u;
        __syncthreads();
    }
    if (t < SB) g_bpre[t] = sh[t] - v;  // exclusive
}

__global__ void __launch_bounds__(256) k_scan3() {
    __shared__ int sh[256];
    int t = threadIdx.x, b = blockIdx.x;
    int i = b * NPB + t;
    int d = (t < NPB) ? g_deg[i] : 0;
    sh[t] = d;
    __syncthreads();
    for (int off = 1; off < 256; off <<= 1) {
        int u = (t >= off) ? sh[t - off] : 0;
        __syncthreads();
        sh[t] += u;
        __syncthreads();
    }
    if (t < NPB) {
        g_rowstart[i] = g_bpre[b] + sh[t] - d;
        g_dinv[i] = rsqrtf((float)(d + 1));  // +1 self loop
        g_fill[i] = 0;
    }
    if (b == SB - 1 && t == 0) g_rowstart[N_] = E_;
}

__global__ void k_csr() {
    int i = blockIdx.x * 256 + threadIdx.x;
    if (i >= E_) return;
    int d = g_dst[i];
    int pos = g_rowstart[d] + atomicAdd(&g_fill[d], 1);
    g_esrc[pos] = g_src[i];
}

// ---------------- conversions -----------------------------------------------
__global__ void k_x2h(const float* __restrict__ x, __half* __restrict__ xh) {
    int i = blockIdx.x * 256 + threadIdx.x;
    if (i < N_ * 32) {
        float4 v = *(const float4*)(x + (size_t)i * 4);
        *(uint2*)(xh + (size_t)i * 4) = f4_to_h4(v);
    }
}

// W [128, CO] fp32 -> Wt [CO][128] fp16 (transposed, K-contiguous)
__global__ void k_wcvt(const float* __restrict__ W, __half* __restrict__ Wt, int CO) {
    int idx = blockIdx.x * 256 + threadIdx.x;
    if (idx >= CO * 128) return;
    int n = idx >> 7, k = idx & 127;
    Wt[idx] = __float2half(W[(size_t)k * CO + n]);
}

// va[j][k] = sum_c W[k][h*C + c] * a[h][c]; j: 0,1=src h0,h1; 2,3=dst h0,h1
__global__ void k_va(const float* __restrict__ W, const float* __restrict__ asrc,
                     const float* __restrict__ adst, int CO, int C) {
    int j = blockIdx.x, k = threadIdx.x;
    const float* a = (j < 2) ? asrc : adst;
    int h = j & 1;
    float s = 0.f;
    for (int c = 0; c < C; c++) s += W[(size_t)k * CO + h * C + c] * a[h * C + c];
    g_va[j * 128 + k] = s;
}

// attention logits for x (input features) — used once for layer GAT... fused
// elsewhere; standalone version retained for the first GCN which feeds GAT1?
// (Not needed: both GAT layers' logits are computed in the GCN gathers.)

// ---- HMMA GEMM: Ch[N,CO] = A[N,128](fp16) @ Wt[CO,128](fp16)^T (fp16 out) --
__global__ void __launch_bounds__(256) k_gemm_h(const __half* __restrict__ A,
                                                const __half* __restrict__ Wt,
                                                __half* __restrict__ Ch, int CO) {
    __shared__ __half As[128 * 128];  // row r: granule g stored at (g ^ (r&7))
    __shared__ __half Bs[64 * 128];
    const int bm = blockIdx.x * 128, bn = blockIdx.y * 64;
    const int tid = threadIdx.x;
    const int warp = tid >> 5, lane = tid & 31;

    {
        int r = tid >> 1, hh = tid & 1;
        int gr = bm + r;
        const uint4* src = (const uint4*)(A + (size_t)gr * 128 + hh * 64);
        uint4 z = make_uint4(0, 0, 0, 0);
#pragma unroll
        for (int g = 0; g < 8; g++) {
            int gg = hh * 8 + g;
            uint4 v = (gr < N_) ? src[g] : z;
            *(uint4*)&As[r * 128 + ((gg ^ (r & 7)) << 3)] = v;
        }
    }
    {
        int n = tid >> 2, q = tid & 3;
        const uint4* src = (const uint4*)(Wt + (size_t)(bn + n) * 128 + q * 32);
#pragma unroll
        for (int g = 0; g < 4; g++) {
            int gg = q * 4 + g;
            uint4 v = src[g];
            *(uint4*)&Bs[n * 128 + ((gg ^ (n & 7)) << 3)] = v;
        }
    }
    __syncthreads();

    const uint32_t sA = smem_u32(As), sB = smem_u32(Bs);
    const int wm = (warp & 3) * 32, wn = (warp >> 2) * 32;
    float acc[2][4][4];
#pragma unroll
    for (int mt = 0; mt < 2; mt++)
#pragma unroll
        for (int nt = 0; nt < 4; nt++)
#pragma unroll
            for (int i = 0; i < 4; i++) acc[mt][nt][i] = 0.f;

#pragma unroll
    for (int kk = 0; kk < 8; kk++) {
        uint32_t a[2][4];
#pragma unroll
        for (int mt = 0; mt < 2; mt++) {
            int r = wm + mt * 16 + (lane & 15);
            int kg = kk * 2 + (lane >> 4);
            ldm4(a[mt][0], a[mt][1], a[mt][2], a[mt][3],
                 sA + (uint32_t)(r * 128 + ((kg ^ (r & 7)) << 3)) * 2);
        }
        uint32_t b[2][4];
#pragma unroll
        for (int nt2 = 0; nt2 < 2; nt2++) {
            int n = wn + nt2 * 16 + (lane & 7) + ((lane >> 4) << 3);
            int kg = kk * 2 + ((lane >> 3) & 1);
            ldm4(b[nt2][0], b[nt2][1], b[nt2][2], b[nt2][3],
                 sB + (uint32_t)(n * 128 + ((kg ^ (n & 7)) << 3)) * 2);
        }
#pragma unroll
        for (int mt = 0; mt < 2; mt++)
#pragma unroll
            for (int nt = 0; nt < 4; nt++) {
                int nt2 = nt >> 1, sub = nt & 1;
                mma16816(acc[mt][nt], a[mt], b[nt2][sub * 2], b[nt2][sub * 2 + 1]);
            }
    }

#pragma unroll
    for (int mt = 0; mt < 2; mt++) {
        int r0 = bm + wm + mt * 16 + (lane >> 2);
#pragma unroll
        for (int half = 0; half < 2; half++) {
            int r = r0 + half * 8;
            if (r < N_) {
#pragma unroll
                for (int nt = 0; nt < 4; nt++) {
                    int cc = bn + wn + nt * 8 + (lane & 3) * 2;
                    *(__half2*)(Ch + (size_t)r * CO + cc) =
                        __floats2half2_rn(acc[mt][nt][half * 2],
                                          acc[mt][nt][half * 2 + 1]);
                }
            }
        }
    }
}

// ------- GCN aggregate + bias + BN + ReLU + NEXT-LAYER attention logits -----
__global__ void __launch_bounds__(256) k_gcn_gather(
    const __half* __restrict__ hh, __half* __restrict__ outh,
    const float* __restrict__ bias, const float* __restrict__ gamma,
    const float* __restrict__ beta, const float* __restrict__ mean,
    const float* __restrict__ var) {
    int n = (blockIdx.x * 256 + threadIdx.x) >> 5;
    if (n >= N_) return;
    int lane = threadIdx.x & 31, c = lane * 4;
    float din = g_dinv[n];
    float ws = din * din;
    float4 acc = ld_h4(hh + (size_t)n * 128 + c);  // self (fp16)
    acc.x *= ws; acc.y *= ws; acc.z *= ws; acc.w *= ws;
    int beg = g_rowstart[n];
    int deg = g_rowstart[n + 1] - beg;
    for (int base = 0; base < deg; base += 32) {
        int cnt = min(32, deg - base);
        int s = 0; float w = 0.f;
        if (lane < cnt) { s = g_esrc[beg + base + lane]; w = g_dinv[s] * din; }
        for (int j = 0; j < cnt; j++) {
            int sj = __shfl_sync(0xffffffffu, s, j);
            float wj = __shfl_sync(0xffffffffu, w, j);
            float4 v = ld_h4(hh + (size_t)sj * 128 + c);
            acc.x += wj * v.x; acc.y += wj * v.y;
            acc.z += wj * v.z; acc.w += wj * v.w;
        }
    }
    float4 o;
    float* ap = &acc.x; float* op = &o.x;
#pragma unroll
    for (int i = 0; i < 4; i++) {
        int ci = c + i;
        float v = ap[i] + bias[ci];
        v = (v - mean[ci]) * rsqrtf(var[ci] + 1e-5f) * gamma[ci] + beta[ci];
        op[i] = fmaxf(v, 0.f);
    }
    *(uint2*)(outh + (size_t)n * 128 + c) = f4_to_h4(o);

    // fused attention logits for the following GAT layer: al[j] = o . va[j]
    float r[4];
#pragma unroll
    for (int j = 0; j < 4; j++) {
        const float4 vv = *(const float4*)&g_va[j * 128 + c];
        float s = o.x * vv.x + o.y * vv.y + o.z * vv.z + o.w * vv.w;
        r[j] = wred_sum(s);
    }
    if (lane == 0) {
        g_als[n * 2 + 0] = r[0]; g_als[n * 2 + 1] = r[1];
        g_ald[n * 2 + 0] = r[2]; g_ald[n * 2 + 1] = r[3];
    }
}

// ------- GAT aggregate, C=128, SINGLE PASS (m=0) + head-mean + bias + ReLU --
__global__ void __launch_bounds__(256) k_gat_gather128(
    const __half* __restrict__ hgh, __half* __restrict__ outh,
    const float* __restrict__ bias) {
    int n = (blockIdx.x * 256 + threadIdx.x) >> 5;
    if (n >= N_) return;
    int lane = threadIdx.x & 31, c = lane * 4;
    float ald0 = g_ald[n * 2], ald1 = g_ald[n * 2 + 1];
    float den0 = __expf(lrelu(g_als[n * 2] + ald0));
    float den1 = __expf(lrelu(g_als[n * 2 + 1] + ald1));
    int beg = g_rowstart[n];
    int deg = g_rowstart[n + 1] - beg;

    const __half* hn = hgh + (size_t)n * 256;  // self (fp16)
    float4 a0 = ld_h4(hn + c);
    float4 a1 = ld_h4(hn + 128 + c);
    float4 acc0 = make_float4(den0 * a0.x, den0 * a0.y, den0 * a0.z, den0 * a0.w);
    float4 acc1 = make_float4(den1 * a1.x, den1 * a1.y, den1 * a1.z, den1 * a1.w);

    for (int base = 0; base < deg; base += 32) {
        int cnt = min(32, deg - base);
        int s = 0; float w0 = 0.f, w1 = 0.f;
        if (lane < cnt) {
            s = g_esrc[beg + base + lane];
            float2 al = *(const float2*)&g_als[2 * s];
            w0 = __expf(lrelu(al.x + ald0));
            w1 = __expf(lrelu(al.y + ald1));
        }
        den0 += wred_sum(w0); den1 += wred_sum(w1);
        for (int j = 0; j < cnt; j++) {
            int sj = __shfl_sync(0xffffffffu, s, j);
            float w0j = __shfl_sync(0xffffffffu, w0, j);
            float w1j = __shfl_sync(0xffffffffu, w1, j);
            const __half* hs = hgh + (size_t)sj * 256;
            float4 v0 = ld_h4(hs + c);
            float4 v1 = ld_h4(hs + 128 + c);
            acc0.x += w0j * v0.x; acc0.y += w0j * v0.y;
            acc0.z += w0j * v0.z; acc0.w += w0j * v0.w;
            acc1.x += w1j * v1.x; acc1.y += w1j * v1.y;
            acc1.z += w1j * v1.z; acc1.w += w1j * v1.w;
        }
    }
    float r0 = 0.5f / den0, r1 = 0.5f / den1;
    float4 o;
    o.x = fmaxf(acc0.x * r0 + acc1.x * r1 + bias[c + 0], 0.f);
    o.y = fmaxf(acc0.y * r0 + acc1.y * r1 + bias[c + 1], 0.f);
    o.z = fmaxf(acc0.z * r0 + acc1.z * r1 + bias[c + 2], 0.f);
    o.w = fmaxf(acc0.w * r0 + acc1.w * r1 + bias[c + 3], 0.f);
    *(uint2*)(outh + (size_t)n * 128 + c) = f4_to_h4(o);
}

// ------- GAT aggregate, C=64, SINGLE PASS + bias + log_softmax --------------
__global__ void __launch_bounds__(256) k_gat_gather64(
    const __half* __restrict__ hgh,
    float* __restrict__ out, const float* __restrict__ bias) {
    int n = (blockIdx.x * 256 + threadIdx.x) >> 5;
    if (n >= N_) return;
    int lane = threadIdx.x & 31;
    int h = lane >> 4, cl = lane & 15, c = cl * 4;
    float ald = g_ald[n * 2 + h];
    float den = __expf(lrelu(g_als[n * 2 + h] + ald));
    int beg = g_rowstart[n];
    int deg = g_rowstart[n + 1] - beg;

    const __half* hn = hgh + (size_t)n * 128 + h * 64;  // self (fp16)
    float4 a = ld_h4(hn + c);
    float4 acc = make_float4(den * a.x, den * a.y, den * a.z, den * a.w);

    for (int base = 0; base < deg; base += 16) {
        int cnt = min(16, deg - base);
        int s = 0; float w = 0.f;
        if (cl < cnt) {
            s = g_esrc[beg + base + cl];
            w = __expf(lrelu(g_als[2 * s + h] + ald));
        }
        float t = w;
#pragma unroll
        for (int off = 8; off; off >>= 1) t += __shfl_xor_sync(0xffffffffu, t, off);
        den += t;
        for (int j = 0; j < cnt; j++) {
            int sj = __shfl_sync(0xffffffffu, s, (h << 4) | j);
            float wj = __shfl_sync(0xffffffffu, w, (h << 4) | j);
            float4 v = ld_h4(hgh + (size_t)sj * 128 + h * 64 + c);
            acc.x += wj * v.x; acc.y += wj * v.y;
            acc.z += wj * v.z; acc.w += wj * v.w;
        }
    }
    float inv = 1.f / den;
    float4 v = make_float4(acc.x * inv, acc.y * inv, acc.z * inv, acc.w * inv);
    float4 o;
    o.x = 0.5f * (v.x + __shfl_xor_sync(0xffffffffu, v.x, 16)) + bias[c + 0];
    o.y = 0.5f * (v.y + __shfl_xor_sync(0xffffffffu, v.y, 16)) + bias[c + 1];
    o.z = 0.5f * (v.z + __shfl_xor_sync(0xffffffffu, v.z, 16)) + bias[c + 2];
    o.w = 0.5f * (v.w + __shfl_xor_sync(0xffffffffu, v.w, 16)) + bias[c + 3];
    float lm = fmaxf(fmaxf(o.x, o.y), fmaxf(o.z, o.w));
#pragma unroll
    for (int off = 8; off; off >>= 1) lm = fmaxf(lm, __shfl_xor_sync(0xffffffffu, lm, off));
    float sum = __expf(o.x - lm) + __expf(o.y - lm) + __expf(o.z - lm) + __expf(o.w - lm);
#pragma unroll
    for (int off = 8; off; off >>= 1) sum += __shfl_xor_sync(0xffffffffu, sum, off);
    float l = lm + logf(sum);
    if (lane < 16) {
        float4 r = make_float4(o.x - l, o.y - l, o.z - l, o.w - l);
        *(float4*)(out + (size_t)n * 64 + c) = r;
    }
}

// ---------------- launch -----------------------------------------------------
extern "C" void kernel_launch(void* const* d_in, const int* in_sizes, int n_in,
                              void* d_out, int out_size) {
    const float* x   = (const float*)d_in[0];
    const void*  ei  = d_in[1];
    const float* Wg1 = (const float*)d_in[2];
    const float* bg1 = (const float*)d_in[3];
    const float* g1g = (const float*)d_in[4];
    const float* g1b = (const float*)d_in[5];
    const float* g1m = (const float*)d_in[6];
    const float* g1v = (const float*)d_in[7];
    const float* Wa1 = (const float*)d_in[8];
    const float* as1 = (const float*)d_in[9];
    const float* ad1 = (const float*)d_in[10];
    const float* ba1 = (const float*)d_in[11];
    const float* Wg2 = (const float*)d_in[12];
    const float* bg2 = (const float*)d_in[13];
    const float* g2g = (const float*)d_in[14];
    const float* g2b = (const float*)d_in[15];
    const float* g2m = (const float*)d_in[16];
    const float* g2v = (const float*)d_in[17];
    const float* Wa2 = (const float*)d_in[18];
    const float* as2 = (const float*)d_in[19];
    const float* ad2 = (const float*)d_in[20];
    const float* ba2 = (const float*)d_in[21];
    float* out = (float*)d_out;

    __half *bufAh, *bufCh, *wt, *xh;
    cudaGetSymbolAddress((void**)&bufAh, g_bufAh);
    cudaGetSymbolAddress((void**)&bufCh, g_bufCh);
    cudaGetSymbolAddress((void**)&wt, g_wt);
    cudaGetSymbolAddress((void**)&xh, g_xh);

    const int TB = 256;
    const int nb = (N_ + TB - 1) / TB;
    const int eb = (E_ + TB - 1) / TB;
    const int nw = (N_ * 32 + TB - 1) / TB;   // warp per node
    const int GX = (N_ + 127) / 128;          // 391 GEMM row tiles

    // ---- preprocessing: dtype detect, deg, CSR (parallel scan)
    k_prep<<<nb, TB>>>(ei);
    k_convert<<<eb, TB>>>(ei);
    k_scan1<<<SB, TB>>>();
    k_scan2<<<1, TB>>>();
    k_scan3<<<SB, TB>>>();
    k_csr<<<eb, TB>>>();
    k_x2h<<<(N_ * 32 + TB - 1) / TB, TB>>>(x, xh);

    // ---- GCN1 (+ bias + BN1 + ReLU + GAT1 logits fused into gather)
    k_wcvt<<<(128 * 128) / TB, TB>>>(Wg1, wt, 128);
    k_gemm_h<<<dim3(GX, 2), TB>>>(xh, wt, bufAh, 128);
    k_va<<<4, 128>>>(Wa1, as1, ad1, 256, 128);
    k_gcn_gather<<<nw, TB>>>(bufAh, bufCh, bg1, g1g, g1b, g1m, g1v);

    // ---- GAT1 (single-pass softmax + head-mean + bias + ReLU fused)
    k_wcvt<<<(256 * 128) / TB, TB>>>(Wa1, wt, 256);
    k_gemm_h<<<dim3(GX, 4), TB>>>(bufCh, wt, bufAh, 256);
    k_gat_gather128<<<nw, TB>>>(bufAh, bufCh, ba1);

    // ---- GCN2 (+ bias + BN2 + ReLU + GAT2 logits fused into gather)
    k_wcvt<<<(128 * 128) / TB, TB>>>(Wg2, wt, 128);
    k_gemm_h<<<dim3(GX, 2), TB>>>(bufCh, wt, bufAh, 128);
    k_va<<<4, 128>>>(Wa2, as2, ad2, 128, 64);
    k_gcn_gather<<<nw, TB>>>(bufAh, bufCh, bg2, g2g, g2b, g2m, g2v);

    // ---- GAT2 (single-pass softmax + head-mean + bias + log_softmax fused)
    k_wcvt<<<(128 * 128) / TB, TB>>>(Wa2, wt, 128);
    k_gemm_h<<<dim3(GX, 2), TB>>>(bufCh, wt, bufAh, 128);
    k_gat_gather64<<<nw, TB>>>(bufAh, out, ba2);
}

// round 12
// speedup vs baseline: 2.8962x; 1.0732x over previous
#include <cuda_runtime.h>
#include <cuda_fp16.h>
#include <math.h>
#include <stddef.h>
#include <stdint.h>

#define N_ 50000
#define E_ 600000
#define SB 200     // scan blocks
#define NPB 250    // nodes per scan block (200*250 = 50000)

// ---------------- device scratch (no allocations allowed) -------------------
__device__ int      g_src[E_];
__device__ int      g_dst[E_];
__device__ int      g_esrc[E_];         // CSR: src ids grouped by dst
__device__ int      g_rowstart[N_ + 1]; // CSR offsets
__device__ int      g_deg[N_];
__device__ int      g_fill[N_];
__device__ int      g_bsum[SB];
__device__ int      g_bpre[SB];
__device__ float    g_dinv[N_];
__device__ int      g_flag;             // 1 = edge_index is int64, 0 = int32
__device__ float    g_als[N_ * 2];
__device__ float    g_ald[N_ * 2];
__device__ float    g_va[8 * 128];      // folded attention W@a (rows 0-3: L1, 4-7: L2)
__device__ __half   g_wt[640 * 128];    // all 4 transposed fp16 weights
__device__ __half   g_xh[N_ * 128];     // fp16 copy of input x
__device__ __half   g_bufAh[N_ * 256];  // GEMM outputs fp16
__device__ __half   g_bufCh[N_ * 128];  // activations fp16 (GEMM feed)

// weight row offsets in g_wt: Wg1 @0 (128 rows), Wa1 @128 (256), Wg2 @384, Wa2 @512
#define WT_G1 0
#define WT_A1 (128 * 128)
#define WT_G2 (384 * 128)
#define WT_A2 (512 * 128)

// ---------------- helpers ---------------------------------------------------
__device__ __forceinline__ float lrelu(float e) { return e > 0.f ? e : 0.2f * e; }

__device__ __forceinline__ float wred_sum(float v) {
#pragma unroll
    for (int o = 16; o; o >>= 1) v += __shfl_xor_sync(0xffffffffu, v, o);
    return v;
}
// 16-lane group sum (offsets 8..1) under a group mask
__device__ __forceinline__ float gred_sum(float v, unsigned m) {
#pragma unroll
    for (int o = 8; o; o >>= 1) v += __shfl_xor_sync(m, v, o);
    return v;
}

__device__ __forceinline__ void ld8(float* v, const __half* p) {  // 8 halves -> 8 floats
    uint4 u = *(const uint4*)p;
    const __half2* h = (const __half2*)&u;
#pragma unroll
    for (int i = 0; i < 4; i++) {
        float2 f = __half22float2(h[i]);
        v[2 * i] = f.x; v[2 * i + 1] = f.y;
    }
}
__device__ __forceinline__ void st8h(__half* p, const float* v) {  // 8 floats -> 8 halves
    uint4 u;
    __half2* h = (__half2*)&u;
#pragma unroll
    for (int i = 0; i < 4; i++) h[i] = __floats2half2_rn(v[2 * i], v[2 * i + 1]);
    *(uint4*)p = u;
}
__device__ __forceinline__ uint2 f4_to_h4(float4 v) {
    __half2 h0 = __floats2half2_rn(v.x, v.y);
    __half2 h1 = __floats2half2_rn(v.z, v.w);
    uint2 u;
    u.x = *(unsigned*)&h0; u.y = *(unsigned*)&h1;
    return u;
}
__device__ __forceinline__ uint32_t smem_u32(const void* p) {
    return (uint32_t)__cvta_generic_to_shared(p);
}
__device__ __forceinline__ void ldm4(uint32_t& r0, uint32_t& r1, uint32_t& r2,
                                     uint32_t& r3, uint32_t addr) {
    asm volatile("ldmatrix.sync.aligned.m8n8.x4.shared.b16 {%0,%1,%2,%3}, [%4];"
                 : "=r"(r0), "=r"(r1), "=r"(r2), "=r"(r3) : "r"(addr));
}
__device__ __forceinline__ void mma16816(float* d, const uint32_t* a,
                                         uint32_t b0, uint32_t b1) {
    asm volatile(
        "mma.sync.aligned.m16n8k16.row.col.f32.f16.f16.f32 "
        "{%0,%1,%2,%3}, {%4,%5,%6,%7}, {%8,%9}, {%0,%1,%2,%3};"
        : "+f"(d[0]), "+f"(d[1]), "+f"(d[2]), "+f"(d[3])
        : "r"(a[0]), "r"(a[1]), "r"(a[2]), "r"(a[3]), "r"(b0), "r"(b1));
}

// ---------------- preprocessing ---------------------------------------------
// fused: deg zero + dtype detect + x -> fp16
__global__ void k_prep_all(const void* eidx, const float* __restrict__ x,
                           __half* __restrict__ xh) {
    int i = blockIdx.x * 256 + threadIdx.x;
    if (i < N_) g_deg[i] = 0;
    if (i < N_ * 32) {
        float4 v = *(const float4*)(x + (size_t)i * 4);
        *(uint2*)(xh + (size_t)i * 4) = f4_to_h4(v);
    }
    if (i == 0) {
        const long long* p = (const long long*)eidx;
        int ok = 1;
        for (int j = 0; j < 128; j++) {
            long long v = p[j];
            if (v < 0 || v >= N_) { ok = 0; break; }
        }
        g_flag = ok;
    }
}

__global__ void k_convert(const void* eidx) {
    int i = blockIdx.x * 256 + threadIdx.x;
    if (i >= E_) return;
    int s, d;
    if (g_flag) {
        const long long* p = (const long long*)eidx;
        s = (int)p[i]; d = (int)p[E_ + i];
    } else {
        const int* p = (const int*)eidx;
        s = p[i]; d = p[E_ + i];
    }
    g_src[i] = s; g_dst[i] = d;
    atomicAdd(&g_deg[d], 1);
}

__global__ void __launch_bounds__(256) k_scan1() {
    __shared__ int sh[256];
    int t = threadIdx.x, b = blockIdx.x;
    int i = b * NPB + t;
    sh[t] = (t < NPB) ? g_deg[i] : 0;
    __syncthreads();
    for (int off = 128; off; off >>= 1) {
        if (t < off) sh[t] += sh[t + off];
        __syncthreads();
    }
    if (t == 0) g_bsum[b] = sh[0];
}

__global__ void __launch_bounds__(256) k_scan2() {
    __shared__ int sh[256];
    int t = threadIdx.x;
    int v = (t < SB) ? g_bsum[t] : 0;
    sh[t] = v;
    __syncthreads();
    for (int off = 1; off < 256; off <<= 1) {
        int u = (t >= off) ? sh[t - off] : 0;
        __syncthreads();
        sh[t] += u;
        __syncthreads();
    }
    if (t < SB) g_bpre[t] = sh[t] - v;  // exclusive
}

__global__ void __launch_bounds__(256) k_scan3() {
    __shared__ int sh[256];
    int t = threadIdx.x, b = blockIdx.x;
    int i = b * NPB + t;
    int d = (t < NPB) ? g_deg[i] : 0;
    sh[t] = d;
    __syncthreads();
    for (int off = 1; off < 256; off <<= 1) {
        int u = (t >= off) ? sh[t - off] : 0;
        __syncthreads();
        sh[t] += u;
        __syncthreads();
    }
    if (t < NPB) {
        g_rowstart[i] = g_bpre[b] + sh[t] - d;
        g_dinv[i] = rsqrtf((float)(d + 1));  // +1 self loop
        g_fill[i] = 0;
    }
    if (b == SB - 1 && t == 0) g_rowstart[N_] = E_;
}

__global__ void k_csr() {
    int i = blockIdx.x * 256 + threadIdx.x;
    if (i >= E_) return;
    int d = g_dst[i];
    int pos = g_rowstart[d] + atomicAdd(&g_fill[d], 1);
    g_esrc[pos] = g_src[i];
}

// ---------------- weight conversions (all 4 matrices, one kernel) -----------
__global__ void k_wcvt_all(const float* __restrict__ Wg1, const float* __restrict__ Wa1,
                           const float* __restrict__ Wg2, const float* __restrict__ Wa2) {
    int idx = blockIdx.x * 256 + threadIdx.x;
    if (idx >= 640 * 128) return;
    int row = idx >> 7, k = idx & 127;
    const float* W; int co, n;
    if (row < 128)      { W = Wg1; co = 128; n = row; }
    else if (row < 384) { W = Wa1; co = 256; n = row - 128; }
    else if (row < 512) { W = Wg2; co = 128; n = row - 384; }
    else                { W = Wa2; co = 128; n = row - 512; }
    g_wt[idx] = __float2half(W[(size_t)k * co + n]);
}

// folded attention vectors for both layers: rows 0-3 (L1), 4-7 (L2)
__global__ void k_va_all(const float* __restrict__ Wa1, const float* __restrict__ as1,
                         const float* __restrict__ ad1, const float* __restrict__ Wa2,
                         const float* __restrict__ as2, const float* __restrict__ ad2) {
    int j = blockIdx.x, k = threadIdx.x;
    const float* W; const float* a; int co, C;
    int jj = j & 3;
    if (j < 4) { W = Wa1; a = (jj < 2) ? as1 : ad1; co = 256; C = 128; }
    else       { W = Wa2; a = (jj < 2) ? as2 : ad2; co = 128; C = 64; }
    int h = jj & 1;
    float s = 0.f;
    for (int c = 0; c < C; c++) s += W[(size_t)k * co + h * C + c] * a[h * C + c];
    g_va[j * 128 + k] = s;
}

// ---- HMMA GEMM: Ch[N,CO] = A[N,128](fp16) @ Wt[CO,128](fp16)^T (fp16 out) --
__global__ void __launch_bounds__(256) k_gemm_h(const __half* __restrict__ A,
                                                const __half* __restrict__ Wt,
                                                __half* __restrict__ Ch, int CO) {
    __shared__ __half As[128 * 128];  // row r: granule g stored at (g ^ (r&7))
    __shared__ __half Bs[64 * 128];
    const int bm = blockIdx.x * 128, bn = blockIdx.y * 64;
    const int tid = threadIdx.x;
    const int warp = tid >> 5, lane = tid & 31;

    {
        int r = tid >> 1, hh = tid & 1;
        int gr = bm + r;
        const uint4* src = (const uint4*)(A + (size_t)gr * 128 + hh * 64);
        uint4 z = make_uint4(0, 0, 0, 0);
#pragma unroll
        for (int g = 0; g < 8; g++) {
            int gg = hh * 8 + g;
            uint4 v = (gr < N_) ? src[g] : z;
            *(uint4*)&As[r * 128 + ((gg ^ (r & 7)) << 3)] = v;
        }
    }
    {
        int n = tid >> 2, q = tid & 3;
        const uint4* src = (const uint4*)(Wt + (size_t)(bn + n) * 128 + q * 32);
#pragma unroll
        for (int g = 0; g < 4; g++) {
            int gg = q * 4 + g;
            uint4 v = src[g];
            *(uint4*)&Bs[n * 128 + ((gg ^ (n & 7)) << 3)] = v;
        }
    }
    __syncthreads();

    const uint32_t sA = smem_u32(As), sB = smem_u32(Bs);
    const int wm = (warp & 3) * 32, wn = (warp >> 2) * 32;
    float acc[2][4][4];
#pragma unroll
    for (int mt = 0; mt < 2; mt++)
#pragma unroll
        for (int nt = 0; nt < 4; nt++)
#pragma unroll
            for (int i = 0; i < 4; i++) acc[mt][nt][i] = 0.f;

#pragma unroll
    for (int kk = 0; kk < 8; kk++) {
        uint32_t a[2][4];
#pragma unroll
        for (int mt = 0; mt < 2; mt++) {
            int r = wm + mt * 16 + (lane & 15);
            int kg = kk * 2 + (lane >> 4);
            ldm4(a[mt][0], a[mt][1], a[mt][2], a[mt][3],
                 sA + (uint32_t)(r * 128 + ((kg ^ (r & 7)) << 3)) * 2);
        }
        uint32_t b[2][4];
#pragma unroll
        for (int nt2 = 0; nt2 < 2; nt2++) {
            int n = wn + nt2 * 16 + (lane & 7) + ((lane >> 4) << 3);
            int kg = kk * 2 + ((lane >> 3) & 1);
            ldm4(b[nt2][0], b[nt2][1], b[nt2][2], b[nt2][3],
                 sB + (uint32_t)(n * 128 + ((kg ^ (n & 7)) << 3)) * 2);
        }
#pragma unroll
        for (int mt = 0; mt < 2; mt++)
#pragma unroll
            for (int nt = 0; nt < 4; nt++) {
                int nt2 = nt >> 1, sub = nt & 1;
                mma16816(acc[mt][nt], a[mt], b[nt2][sub * 2], b[nt2][sub * 2 + 1]);
            }
    }

#pragma unroll
    for (int mt = 0; mt < 2; mt++) {
        int r0 = bm + wm + mt * 16 + (lane >> 2);
#pragma unroll
        for (int half = 0; half < 2; half++) {
            int r = r0 + half * 8;
            if (r < N_) {
#pragma unroll
                for (int nt = 0; nt < 4; nt++) {
                    int cc = bn + wn + nt * 8 + (lane & 3) * 2;
                    *(__half2*)(Ch + (size_t)r * CO + cc) =
                        __floats2half2_rn(acc[mt][nt][half * 2],
                                          acc[mt][nt][half * 2 + 1]);
                }
            }
        }
    }
}

// ------- GCN aggregate: 2 nodes/warp, 16 lanes/node, 16B loads --------------
// + bias + BN + ReLU + next-GAT attention logits
__global__ void __launch_bounds__(256) k_gcn_gather(
    const __half* __restrict__ hh, __half* __restrict__ outh,
    const float* __restrict__ bias, const float* __restrict__ gamma,
    const float* __restrict__ beta, const float* __restrict__ mean,
    const float* __restrict__ var, int vaOff) {
    int gw = (blockIdx.x * 256 + threadIdx.x) >> 5;
    if (gw * 2 >= N_) return;
    int lane = threadIdx.x & 31;
    int g = lane >> 4, cl = lane & 15;
    int n = gw * 2 + g;                       // N_ even -> always valid
    unsigned gmask = 0xFFFFu << (g * 16);
    int cb = cl * 8;                          // 8 channels per lane

    float din = g_dinv[n];
    float ws = din * din;
    float acc[8];
    ld8(acc, hh + (size_t)n * 128 + cb);
#pragma unroll
    for (int i = 0; i < 8; i++) acc[i] *= ws;

    int beg = g_rowstart[n];
    int deg = g_rowstart[n + 1] - beg;
    for (int base = 0; base < deg; base += 16) {
        int cnt = min(16, deg - base);
        int s = 0; float w = 0.f;
        if (cl < cnt) { s = g_esrc[beg + base + cl]; w = g_dinv[s] * din; }
        for (int j = 0; j < cnt; j++) {
            int sj = __shfl_sync(gmask, s, (g << 4) + j);
            float wj = __shfl_sync(gmask, w, (g << 4) + j);
            float v[8];
            ld8(v, hh + (size_t)sj * 128 + cb);
#pragma unroll
            for (int i = 0; i < 8; i++) acc[i] += wj * v[i];
        }
    }
    float o[8];
    float4 b0 = *(const float4*)(bias + cb),  b1 = *(const float4*)(bias + cb + 4);
    float4 gm0 = *(const float4*)(gamma + cb), gm1 = *(const float4*)(gamma + cb + 4);
    float4 bt0 = *(const float4*)(beta + cb),  bt1 = *(const float4*)(beta + cb + 4);
    float4 mn0 = *(const float4*)(mean + cb),  mn1 = *(const float4*)(mean + cb + 4);
    float4 vr0 = *(const float4*)(var + cb),   vr1 = *(const float4*)(var + cb + 4);
    const float* bp = &b0.x; const float* gp = &gm0.x; const float* tp = &bt0.x;
    const float* mp = &mn0.x; const float* vp = &vr0.x;
    (void)b1; (void)gm1; (void)bt1; (void)mn1; (void)vr1;  // contiguous on stack
#pragma unroll
    for (int i = 0; i < 8; i++) {
        float bb = (i < 4) ? (&b0.x)[i] : (&b1.x)[i - 4];
        float gg = (i < 4) ? (&gm0.x)[i] : (&gm1.x)[i - 4];
        float tt = (i < 4) ? (&bt0.x)[i] : (&bt1.x)[i - 4];
        float mm = (i < 4) ? (&mn0.x)[i] : (&mn1.x)[i - 4];
        float vv = (i < 4) ? (&vr0.x)[i] : (&vr1.x)[i - 4];
        float val = acc[i] + bb;
        val = (val - mm) * rsqrtf(vv + 1e-5f) * gg + tt;
        o[i] = fmaxf(val, 0.f);
    }
    (void)bp; (void)gp; (void)tp; (void)mp; (void)vp;
    st8h(outh + (size_t)n * 128 + cb, o);

    // fused attention logits for the following GAT layer
    float r[4];
#pragma unroll
    for (int j = 0; j < 4; j++) {
        const float* vap = g_va + (vaOff + j) * 128 + cb;
        float4 p0 = *(const float4*)vap, p1 = *(const float4*)(vap + 4);
        float s = o[0] * p0.x + o[1] * p0.y + o[2] * p0.z + o[3] * p0.w +
                  o[4] * p1.x + o[5] * p1.y + o[6] * p1.z + o[7] * p1.w;
        r[j] = gred_sum(s, gmask);
    }
    if (cl == 0) {
        g_als[n * 2 + 0] = r[0]; g_als[n * 2 + 1] = r[1];
        g_ald[n * 2 + 0] = r[2]; g_ald[n * 2 + 1] = r[3];
    }
}

// ------- GAT aggregate, C=128: 1 node/warp, 16B loads cover both heads ------
__global__ void __launch_bounds__(256) k_gat_gather128(
    const __half* __restrict__ hgh, __half* __restrict__ outh,
    const float* __restrict__ bias) {
    int n = (blockIdx.x * 256 + threadIdx.x) >> 5;
    if (n >= N_) return;
    int lane = threadIdx.x & 31;
    int h = lane >> 4;                        // head owned by this lane
    int cb = lane * 8;                        // channel base in the 256-wide row

    float ald0 = g_ald[n * 2], ald1 = g_ald[n * 2 + 1];
    float den0 = __expf(lrelu(g_als[n * 2] + ald0));
    float den1 = __expf(lrelu(g_als[n * 2 + 1] + ald1));
    float wself = h ? den1 : den0;

    float acc[8];
    ld8(acc, hgh + (size_t)n * 256 + cb);
#pragma unroll
    for (int i = 0; i < 8; i++) acc[i] *= wself;

    int beg = g_rowstart[n];
    int deg = g_rowstart[n + 1] - beg;
    for (int base = 0; base < deg; base += 32) {
        int cnt = min(32, deg - base);
        int s = 0; float w0 = 0.f, w1 = 0.f;
        if (lane < cnt) {
            s = g_esrc[beg + base + lane];
            float2 al = *(const float2*)&g_als[2 * s];
            w0 = __expf(lrelu(al.x + ald0));
            w1 = __expf(lrelu(al.y + ald1));
        }
        den0 += wred_sum(w0); den1 += wred_sum(w1);
        for (int j = 0; j < cnt; j++) {
            int sj = __shfl_sync(0xffffffffu, s, j);
            float w0j = __shfl_sync(0xffffffffu, w0, j);
            float w1j = __shfl_sync(0xffffffffu, w1, j);
            float wj = h ? w1j : w0j;
            float v[8];
            ld8(v, hgh + (size_t)sj * 256 + cb);
#pragma unroll
            for (int i = 0; i < 8; i++) acc[i] += wj * v[i];
        }
    }
    float r = 0.5f / (h ? den1 : den0);
    float o[8];
#pragma unroll
    for (int i = 0; i < 8; i++) {
        float val = acc[i] * r;
        o[i] = val + __shfl_xor_sync(0xffffffffu, val, 16);  // add other head
    }
    if (lane < 16) {
        int oc = lane * 8;  // output channel base (128-wide)
        float4 b0 = *(const float4*)(bias + oc), b1 = *(const float4*)(bias + oc + 4);
#pragma unroll
        for (int i = 0; i < 8; i++) {
            float bb = (i < 4) ? (&b0.x)[i] : (&b1.x)[i - 4];
            o[i] = fmaxf(o[i] + bb, 0.f);
        }
        st8h(outh + (size_t)n * 128 + oc, o);
    }
}

// ------- GAT aggregate, C=64: 2 nodes/warp + bias + log_softmax -------------
__global__ void __launch_bounds__(256) k_gat_gather64(
    const __half* __restrict__ hgh,
    float* __restrict__ out, const float* __restrict__ bias) {
    int gw = (blockIdx.x * 256 + threadIdx.x) >> 5;
    if (gw * 2 >= N_) return;
    int lane = threadIdx.x & 31;
    int g = lane >> 4, cl = lane & 15;
    int n = gw * 2 + g;
    unsigned gmask = 0xFFFFu << (g * 16);
    int h = cl >> 3;                // head owned by this lane
    int cb = (cl & 7) * 8;          // channel base within head (0..56)

    float ald0 = g_ald[n * 2], ald1 = g_ald[n * 2 + 1];
    float es0 = __expf(lrelu(g_als[n * 2] + ald0));
    float es1 = __expf(lrelu(g_als[n * 2 + 1] + ald1));
    float den = h ? es1 : es0;
    float wself = den;

    float acc[8];
    ld8(acc, hgh + (size_t)n * 128 + cl * 8);  // cl*8 = h*64 + cb
#pragma unroll
    for (int i = 0; i < 8; i++) acc[i] *= wself;

    int beg = g_rowstart[n];
    int deg = g_rowstart[n + 1] - beg;
    for (int base = 0; base < deg; base += 16) {
        int cnt = min(16, deg - base);
        int s = 0; float w0 = 0.f, w1 = 0.f;
        if (cl < cnt) {
            s = g_esrc[beg + base + cl];
            float2 al = *(const float2*)&g_als[2 * s];
            w0 = __expf(lrelu(al.x + ald0));
            w1 = __expf(lrelu(al.y + ald1));
        }
        float sw0 = gred_sum(w0, gmask), sw1 = gred_sum(w1, gmask);
        den += h ? sw1 : sw0;
        for (int j = 0; j < cnt; j++) {
            int sj = __shfl_sync(gmask, s, (g << 4) + j);
            float w0j = __shfl_sync(gmask, w0, (g << 4) + j);
            float w1j = __shfl_sync(gmask, w1, (g << 4) + j);
            float wj = h ? w1j : w0j;
            float v[8];
            ld8(v, hgh + (size_t)sj * 128 + cl * 8);
#pragma unroll
            for (int i = 0; i < 8; i++) acc[i] += wj * v[i];
        }
    }
    float inv = 1.f / den;
    float4 b0 = *(const float4*)(bias + cb), b1 = *(const float4*)(bias + cb + 4);
    float o[8];
#pragma unroll
    for (int i = 0; i < 8; i++) {
        float val = acc[i] * inv;
        float bb = (i < 4) ? (&b0.x)[i] : (&b1.x)[i - 4];
        o[i] = 0.5f * (val + __shfl_xor_sync(gmask, val, 8)) + bb;  // head mean
    }
    // log_softmax over the node's 64 channels (held by 8 lanes x 8 values,
    // duplicated on the other head's lanes)
    float lm = o[0];
#pragma unroll
    for (int i = 1; i < 8; i++) lm = fmaxf(lm, o[i]);
#pragma unroll
    for (int off = 4; off; off >>= 1) lm = fmaxf(lm, __shfl_xor_sync(gmask, lm, off));
    float sum = 0.f;
#pragma unroll
    for (int i = 0; i < 8; i++) sum += __expf(o[i] - lm);
#pragma unroll
    for (int off = 4; off; off >>= 1) sum += __shfl_xor_sync(gmask, sum, off);
    float l = lm + logf(sum);
    if (h == 0) {
        float* op = out + (size_t)n * 64 + cb;
        float4 r0 = make_float4(o[0] - l, o[1] - l, o[2] - l, o[3] - l);
        float4 r1 = make_float4(o[4] - l, o[5] - l, o[6] - l, o[7] - l);
        *(float4*)op = r0;
        *(float4*)(op + 4) = r1;
    }
}

// ---------------- launch -----------------------------------------------------
extern "C" void kernel_launch(void* const* d_in, const int* in_sizes, int n_in,
                              void* d_out, int out_size) {
    const float* x   = (const float*)d_in[0];
    const void*  ei  = d_in[1];
    const float* Wg1 = (const float*)d_in[2];
    const float* bg1 = (const float*)d_in[3];
    const float* g1g = (const float*)d_in[4];
    const float* g1b = (const float*)d_in[5];
    const float* g1m = (const float*)d_in[6];
    const float* g1v = (const float*)d_in[7];
    const float* Wa1 = (const float*)d_in[8];
    const float* as1 = (const float*)d_in[9];
    const float* ad1 = (const float*)d_in[10];
    const float* ba1 = (const float*)d_in[11];
    const float* Wg2 = (const float*)d_in[12];
    const float* bg2 = (const float*)d_in[13];
    const float* g2g = (const float*)d_in[14];
    const float* g2b = (const float*)d_in[15];
    const float* g2m = (const float*)d_in[16];
    const float* g2v = (const float*)d_in[17];
    const float* Wa2 = (const float*)d_in[18];
    const float* as2 = (const float*)d_in[19];
    const float* ad2 = (const float*)d_in[20];
    const float* ba2 = (const float*)d_in[21];
    float* out = (float*)d_out;

    __half *bufAh, *bufCh, *wt, *xh;
    cudaGetSymbolAddress((void**)&bufAh, g_bufAh);
    cudaGetSymbolAddress((void**)&bufCh, g_bufCh);
    cudaGetSymbolAddress((void**)&wt, g_wt);
    cudaGetSymbolAddress((void**)&xh, g_xh);

    const int TB = 256;
    const int eb = (E_ + TB - 1) / TB;
    const int nw1 = (N_ * 32 + TB - 1) / TB;        // 1 node/warp grids
    const int nw2 = ((N_ / 2) * 32 + TB - 1) / TB;  // 2 nodes/warp grids
    const int GX = (N_ + 127) / 128;                // 391 GEMM row tiles

    // ---- preprocessing
    k_prep_all<<<(N_ * 32 + TB - 1) / TB, TB>>>(ei, x, xh);
    k_convert<<<eb, TB>>>(ei);
    k_scan1<<<SB, TB>>>();
    k_scan2<<<1, TB>>>();
    k_scan3<<<SB, TB>>>();
    k_csr<<<eb, TB>>>();
    k_wcvt_all<<<(640 * 128) / TB, TB>>>(Wg1, Wa1, Wg2, Wa2);
    k_va_all<<<8, 128>>>(Wa1, as1, ad1, Wa2, as2, ad2);

    // ---- GCN1 (+ bias + BN1 + ReLU + GAT1 logits)
    k_gemm_h<<<dim3(GX, 2), TB>>>(xh, wt + WT_G1, bufAh, 128);
    k_gcn_gather<<<nw2, TB>>>(bufAh, bufCh, bg1, g1g, g1b, g1m, g1v, 0);

    // ---- GAT1 (single-pass softmax + head-mean + bias + ReLU)
    k_gemm_h<<<dim3(GX, 4), TB>>>(bufCh, wt + WT_A1, bufAh, 256);
    k_gat_gather128<<<nw1, TB>>>(bufAh, bufCh, ba1);

    // ---- GCN2 (+ bias + BN2 + ReLU + GAT2 logits)
    k_gemm_h<<<dim3(GX, 2), TB>>>(bufCh, wt + WT_G2, bufAh, 128);
    k_gcn_gather<<<nw2, TB>>>(bufAh, bufCh, bg2, g2g, g2b, g2m, g2v, 4);

    // ---- GAT2 (single-pass softmax + head-mean + bias + log_softmax)
    k_gemm_h<<<dim3(GX, 2), TB>>>(bufCh, wt + WT_A2, bufAh, 128);
    k_gat_gather64<<<nw2, TB>>>(bufAh, out, ba2);
}